// round 1
// baseline (speedup 1.0000x reference)
#include <cuda_runtime.h>
#include <math.h>

#define NPTS   131072
#define CF     64
#define NCLS   18
#define TILE   128
#define THREADS 256
#define NTILES (NPTS / TILE)
#define VOXEL  0.04f
// logit(0.15) = ln(0.15/0.85)
#define SEM_LOGIT (-1.7346010553881064f)

// out layout: main [NCLS][NPTS][8] followed by voted [NPTS][3]
#define OUT_VOFF ((size_t)NCLS * NPTS * 8)

// smem layout (floats)
#define SF_OFF    0                    // s_feats [64][128] (k-major)
#define SSTG_OFF  (64 * TILE)          // s_stage [64][128] (k-major)
#define SW_OFF    (2 * 64 * TILE)      // s_W     [64][64]
#define SWH_OFF   (SW_OFF + 64 * 64)   // s_Wh    [64][8]
#define SOUT_OFF  (SWH_OFF + 64 * 8)   // s_out   [128][9]
#define SMASK_OFF (SOUT_OFF + TILE * 9)// mask    [128] + orv [1] (as uint)
#define SMEM_FLOATS (SMASK_OFF + 129 + 7)
#define SMEM_BYTES  (SMEM_FLOATS * 4)

__device__ int g_bmin[3];
__device__ int g_bmax[3];

__global__ void k_init_bounds() {
    int t = threadIdx.x;
    if (t < 3) { g_bmin[t] = 0x7fffffff; g_bmax[t] = -0x7fffffff - 1; }
}

__global__ void k_bounds(const int* __restrict__ coords) {
    __shared__ int smin[3], smax[3];
    int tid = threadIdx.x;
    if (tid < 3) { smin[tid] = 0x7fffffff; smax[tid] = -0x7fffffff - 1; }
    __syncthreads();
    int lmin0 = 0x7fffffff, lmin1 = 0x7fffffff, lmin2 = 0x7fffffff;
    int lmax0 = -0x7fffffff - 1, lmax1 = -0x7fffffff - 1, lmax2 = -0x7fffffff - 1;
    for (int i = blockIdx.x * blockDim.x + tid; i < NPTS; i += gridDim.x * blockDim.x) {
        int4 cr = __ldg((const int4*)coords + i);   // [b, x, y, z]
        lmin0 = min(lmin0, cr.y); lmax0 = max(lmax0, cr.y);
        lmin1 = min(lmin1, cr.z); lmax1 = max(lmax1, cr.z);
        lmin2 = min(lmin2, cr.w); lmax2 = max(lmax2, cr.w);
    }
    lmin0 = __reduce_min_sync(0xffffffffu, lmin0);
    lmin1 = __reduce_min_sync(0xffffffffu, lmin1);
    lmin2 = __reduce_min_sync(0xffffffffu, lmin2);
    lmax0 = __reduce_max_sync(0xffffffffu, lmax0);
    lmax1 = __reduce_max_sync(0xffffffffu, lmax1);
    lmax2 = __reduce_max_sync(0xffffffffu, lmax2);
    if ((tid & 31) == 0) {
        atomicMin(&smin[0], lmin0); atomicMax(&smax[0], lmax0);
        atomicMin(&smin[1], lmin1); atomicMax(&smax[1], lmax1);
        atomicMin(&smin[2], lmin2); atomicMax(&smax[2], lmax2);
    }
    __syncthreads();
    if (tid < 3) { atomicMin(&g_bmin[tid], smin[tid]); atomicMax(&g_bmax[tid], smax[tid]); }
}

__device__ __forceinline__ float eluf(float x) { return x > 0.0f ? x : expm1f(x); }

// [128 x 64] (k-major input) x [64 x 64] -> acc[4 points][8 cols]
__device__ __forceinline__ void gemm64(const float* __restrict__ inp,
                                       const float* __restrict__ w,
                                       int tx, int ty, float acc[4][8]) {
#pragma unroll
    for (int p = 0; p < 4; p++)
#pragma unroll
        for (int e = 0; e < 8; e++) acc[p][e] = 0.0f;
    const float* ip = inp + tx * 4;
    const float* wp = w + ty * 8;
#pragma unroll 8
    for (int k = 0; k < CF; k++) {
        float4 f  = *(const float4*)(ip + k * TILE);
        float4 wa = *(const float4*)(wp + k * 64);
        float4 wb = *(const float4*)(wp + k * 64 + 4);
        float fv[4] = {f.x, f.y, f.z, f.w};
        float wv[8] = {wa.x, wa.y, wa.z, wa.w, wb.x, wb.y, wb.z, wb.w};
#pragma unroll
        for (int p = 0; p < 4; p++)
#pragma unroll
            for (int e = 0; e < 8; e++)
                acc[p][e] = fmaf(fv[p], wv[e], acc[p][e]);
    }
}

__global__ __launch_bounds__(THREADS, 2)
void k_main(const int* __restrict__ coords, const float* __restrict__ feats,
            const float* __restrict__ W_sem, const float* __restrict__ b_sem,
            const float* __restrict__ W_o1, const float* __restrict__ g_o1,
            const float* __restrict__ b_o1, const float* __restrict__ W_o2,
            const float* __restrict__ g_o2, const float* __restrict__ b_o2,
            const float* __restrict__ W_o3, const float* __restrict__ W_ci,
            const float* __restrict__ g_ci, const float* __restrict__ b_ci,
            const float* __restrict__ W_ctr, const float* __restrict__ W_reg,
            const float* __restrict__ W_cls, const float* __restrict__ b_cls,
            const float* __restrict__ scales, float* __restrict__ out)
{
    extern __shared__ float sm[];
    float* s_feats = sm + SF_OFF;
    float* s_stage = sm + SSTG_OFF;
    float* s_W     = sm + SW_OFF;
    float* s_Wh    = sm + SWH_OFF;
    float* s_out   = sm + SOUT_OFF;
    unsigned* s_mask = (unsigned*)(sm + SMASK_OFF);
    unsigned* s_orv  = s_mask + TILE;

    const int tid = threadIdx.x;
    const int tx = tid & 31, ty = tid >> 5;
    const int n0 = blockIdx.x * TILE;

    // ---- P0: zero mask, transpose-load feats tile (k-major), stage W_sem ----
    if (tid < TILE) s_mask[tid] = 0u;
    for (int i = tid; i < TILE * 16; i += THREADS) {
        int n = i >> 4, c4 = i & 15;
        float4 v = __ldg((const float4*)(feats + (size_t)(n0 + n) * CF) + c4);
        int k = c4 * 4;
        s_feats[(k + 0) * TILE + n] = v.x;
        s_feats[(k + 1) * TILE + n] = v.y;
        s_feats[(k + 2) * TILE + n] = v.z;
        s_feats[(k + 3) * TILE + n] = v.w;
    }
    for (int i = tid; i < CF * NCLS; i += THREADS) {
        s_W[(i / NCLS) * 64 + (i % NCLS)] = __ldg(W_sem + i);
    }
    __syncthreads();

    // ---- P1: semantic scores -> mask bitmask ----
#pragma unroll
    for (int pass = 0; pass < 3; pass++) {
        int c = ty + pass * 8;
        if (c < NCLS) {
            float bs = __ldg(b_sem + c);
            float a0 = bs, a1 = bs, a2 = bs, a3 = bs;
#pragma unroll 8
            for (int k = 0; k < CF; k++) {
                float4 f = *(const float4*)(s_feats + k * TILE + tx * 4);
                float w = s_W[k * 64 + c];
                a0 = fmaf(f.x, w, a0); a1 = fmaf(f.y, w, a1);
                a2 = fmaf(f.z, w, a2); a3 = fmaf(f.w, w, a3);
            }
            unsigned bit = 1u << c;
            if (a0 > SEM_LOGIT) atomicOr(&s_mask[tx * 4 + 0], bit);
            if (a1 > SEM_LOGIT) atomicOr(&s_mask[tx * 4 + 1], bit);
            if (a2 > SEM_LOGIT) atomicOr(&s_mask[tx * 4 + 2], bit);
            if (a3 > SEM_LOGIT) atomicOr(&s_mask[tx * 4 + 3], bit);
        }
    }
    __syncthreads();
    if (tid < 32) {
        unsigned o = 0;
        for (int j = tid; j < TILE; j += 32) o |= s_mask[j];
        o = __reduce_or_sync(0xffffffffu, o);
        if (tid == 0) *s_orv = o;
    }
    // load W_o1 (different smem region than warp0's reduce)
    for (int i = tid; i < CF * CF / 4; i += THREADS)
        ((float4*)s_W)[i] = __ldg((const float4*)W_o1 + i);
    __syncthreads();

    // ---- P2: offset MLP layer1 ----
    {
        float acc[4][8];
        gemm64(s_feats, s_W, tx, ty, acc);
#pragma unroll
        for (int eo = 0; eo < 8; eo++) {
            int e = ty * 8 + eo;
            float g = __ldg(g_o1 + e), b = __ldg(b_o1 + e);
            float4 o;
            o.x = eluf(fmaf(acc[0][eo], g, b));
            o.y = eluf(fmaf(acc[1][eo], g, b));
            o.z = eluf(fmaf(acc[2][eo], g, b));
            o.w = eluf(fmaf(acc[3][eo], g, b));
            *(float4*)(s_stage + e * TILE + tx * 4) = o;
        }
    }
    __syncthreads();
    for (int i = tid; i < CF * CF / 4; i += THREADS)
        ((float4*)s_W)[i] = __ldg((const float4*)W_o2 + i);
    __syncthreads();
    // layer2 (in-place on s_stage: compute fully, sync, then write)
    {
        float acc[4][8];
        gemm64(s_stage, s_W, tx, ty, acc);
        __syncthreads();
#pragma unroll
        for (int eo = 0; eo < 8; eo++) {
            int e = ty * 8 + eo;
            float g = __ldg(g_o2 + e), b = __ldg(b_o2 + e);
            float4 o;
            o.x = eluf(fmaf(acc[0][eo], g, b));
            o.y = eluf(fmaf(acc[1][eo], g, b));
            o.z = eluf(fmaf(acc[2][eo], g, b));
            o.w = eluf(fmaf(acc[3][eo], g, b));
            *(float4*)(s_stage + e * TILE + tx * 4) = o;
        }
    }
    __syncthreads();
    // layer3: offset (3 cols) + voted clip + store
    for (int idx = tid; idx < TILE * 3; idx += THREADS) {
        int n = idx & (TILE - 1), r = idx >> 7;
        float acc = 0.0f;
#pragma unroll 8
        for (int k = 0; k < CF; k++)
            acc = fmaf(s_stage[k * TILE + n], __ldg(W_o3 + k * 3 + r), acc);
        float xyz = (float)__ldg(coords + (size_t)(n0 + n) * 4 + 1 + r);
        float mnb = (float)(g_bmin[r] - 1) * VOXEL;
        float mxb = (float)(g_bmax[r] + 1) * VOXEL;
        float v = fminf(fmaxf(fmaf(xyz, VOXEL, acc), mnb), mxb);
        out[OUT_VOFF + (size_t)(n0 + n) * 3 + r] = v;
    }

    const unsigned orv = *s_orv;   // written before S3, visible

    // ---- P3: per-class loop ----
    for (int c = 0; c < NCLS; c++) {
        float* outc = out + ((size_t)c * NPTS + n0) * 8;
        if (!((orv >> c) & 1u)) {
            // whole tile masked for this class: feat_c == 0 exactly
            // -> ctr = 0, reg = exp(0) = 1, cls = b_cls[c]
            float bc = __ldg(b_cls + c);
            int n = tid >> 1, h = tid & 1;
            float4 v = h ? make_float4(1.0f, 1.0f, 1.0f, bc)
                         : make_float4(0.0f, 1.0f, 1.0f, 1.0f);
            ((float4*)(outc + n * 8))[h] = v;
            continue;   // uniform branch (orv is block-uniform)
        }
        __syncthreads();   // protect s_W / s_stage / s_out reuse
        const float* Wc = W_ci + (size_t)c * CF * CF;
        for (int i = tid; i < CF * CF / 4; i += THREADS)
            ((float4*)s_W)[i] = __ldg((const float4*)Wc + i);
        for (int i = tid; i < CF * 8; i += THREADS) {
            int k = i >> 3, j = i & 7;
            float w;
            if (j == 0)      w = __ldg(W_ctr + k);
            else if (j < 7)  w = __ldg(W_reg + k * 6 + (j - 1));
            else             w = __ldg(W_cls + k * NCLS + c);
            s_Wh[i] = w;
        }
        __syncthreads();
        // branch GEMM + BN + ELU + mask, staged k-major into s_stage
        {
            float acc[4][8];
            gemm64(s_feats, s_W, tx, ty, acc);
            float m0 = (float)((s_mask[tx * 4 + 0] >> c) & 1u);
            float m1 = (float)((s_mask[tx * 4 + 1] >> c) & 1u);
            float m2 = (float)((s_mask[tx * 4 + 2] >> c) & 1u);
            float m3 = (float)((s_mask[tx * 4 + 3] >> c) & 1u);
#pragma unroll
            for (int eo = 0; eo < 8; eo++) {
                int e = ty * 8 + eo;
                float g = __ldg(g_ci + c * CF + e), b = __ldg(b_ci + c * CF + e);
                float4 o;
                o.x = eluf(fmaf(acc[0][eo], g, b)) * m0;
                o.y = eluf(fmaf(acc[1][eo], g, b)) * m1;
                o.z = eluf(fmaf(acc[2][eo], g, b)) * m2;
                o.w = eluf(fmaf(acc[3][eo], g, b)) * m3;
                *(float4*)(s_stage + e * TILE + tx * 4) = o;
            }
        }
        __syncthreads();
        // head GEMM: 8 output cols, ty = output col
        {
            float a0 = 0.f, a1 = 0.f, a2 = 0.f, a3 = 0.f;
#pragma unroll 8
            for (int k = 0; k < CF; k++) {
                float4 f = *(const float4*)(s_stage + k * TILE + tx * 4);
                float w = s_Wh[k * 8 + ty];
                a0 = fmaf(f.x, w, a0); a1 = fmaf(f.y, w, a1);
                a2 = fmaf(f.z, w, a2); a3 = fmaf(f.w, w, a3);
            }
            float sc = __ldg(scales + c), bc = __ldg(b_cls + c);
            if (ty >= 1 && ty <= 6) {
                a0 = expf(a0 * sc); a1 = expf(a1 * sc);
                a2 = expf(a2 * sc); a3 = expf(a3 * sc);
            } else if (ty == 7) {
                a0 += bc; a1 += bc; a2 += bc; a3 += bc;
            }
            s_out[(tx * 4 + 0) * 9 + ty] = a0;
            s_out[(tx * 4 + 1) * 9 + ty] = a1;
            s_out[(tx * 4 + 2) * 9 + ty] = a2;
            s_out[(tx * 4 + 3) * 9 + ty] = a3;
        }
        __syncthreads();
        {
            int n = tid >> 1, h = tid & 1;
            float4 v;
            v.x = s_out[n * 9 + h * 4 + 0];
            v.y = s_out[n * 9 + h * 4 + 1];
            v.z = s_out[n * 9 + h * 4 + 2];
            v.w = s_out[n * 9 + h * 4 + 3];
            ((float4*)(outc + n * 8))[h] = v;
        }
    }
}

extern "C" void kernel_launch(void* const* d_in, const int* in_sizes, int n_in,
                              void* d_out, int out_size) {
    const int*   coords = (const int*)d_in[0];
    const float* feats  = (const float*)d_in[1];
    const float* W_sem  = (const float*)d_in[2];
    const float* b_sem  = (const float*)d_in[3];
    const float* W_o1   = (const float*)d_in[4];
    const float* g_o1   = (const float*)d_in[5];
    const float* b_o1   = (const float*)d_in[6];
    const float* W_o2   = (const float*)d_in[7];
    const float* g_o2   = (const float*)d_in[8];
    const float* b_o2   = (const float*)d_in[9];
    const float* W_o3   = (const float*)d_in[10];
    const float* W_ci   = (const float*)d_in[11];
    const float* g_ci   = (const float*)d_in[12];
    const float* b_ci   = (const float*)d_in[13];
    const float* W_ctr  = (const float*)d_in[14];
    const float* W_reg  = (const float*)d_in[15];
    const float* W_cls  = (const float*)d_in[16];
    const float* b_cls  = (const float*)d_in[17];
    const float* scales = (const float*)d_in[18];
    float* out = (float*)d_out;

    cudaFuncSetAttribute(k_main, cudaFuncAttributeMaxDynamicSharedMemorySize, SMEM_BYTES);
    k_init_bounds<<<1, 32>>>();
    k_bounds<<<264, 256>>>(coords);
    k_main<<<NTILES, THREADS, SMEM_BYTES>>>(coords, feats, W_sem, b_sem,
        W_o1, g_o1, b_o1, W_o2, g_o2, b_o2, W_o3, W_ci, g_ci, b_ci,
        W_ctr, W_reg, W_cls, b_cls, scales, out);
}

// round 2
// speedup vs baseline: 1.3980x; 1.3980x over previous
#include <cuda_runtime.h>
#include <math.h>

#define NPTS   131072
#define CF     64
#define NCLS   18
#define TILE   128
#define THREADS 256
#define NTILES (NPTS / TILE)
#define VOXEL  0.04f
// logit(0.15) = ln(0.15/0.85)
#define SEM_LOGIT (-1.7346010553881064f)

// out layout: main [NCLS][NPTS][8] followed by voted [NPTS][3]
#define OUT_VOFF ((size_t)NCLS * NPTS * 8)

// smem layout (floats)
#define SF_OFF    0                      // s_feats [64][128] swizzled k-major
#define SSTG_OFF  8192                   // s_stage [128][68] staging / [64][128] MLP
#define SW_OFF    16896                  // s_Wd    [64][128] duplicated weights
#define SWH_OFF   25088                  // s_Wh    [64][8]
#define SOUT_OFF  25600                  // s_out   [128][9]
#define SMASK_OFF 26752                  // mask[128] + orv
#define SMEM_FLOATS (SMASK_OFF + 132)
#define SMEM_BYTES  (SMEM_FLOATS * 4)

typedef unsigned long long ull;

__device__ int g_bmin[3] = {0x7fffffff, 0x7fffffff, 0x7fffffff};
__device__ int g_bmax[3] = {(int)0x80000000, (int)0x80000000, (int)0x80000000};

__global__ void k_bounds(const int* __restrict__ coords) {
    __shared__ int smin[3], smax[3];
    int tid = threadIdx.x;
    if (tid < 3) { smin[tid] = 0x7fffffff; smax[tid] = (int)0x80000000; }
    __syncthreads();
    int lmin0 = 0x7fffffff, lmin1 = 0x7fffffff, lmin2 = 0x7fffffff;
    int lmax0 = (int)0x80000000, lmax1 = (int)0x80000000, lmax2 = (int)0x80000000;
    for (int i = blockIdx.x * blockDim.x + tid; i < NPTS; i += gridDim.x * blockDim.x) {
        int4 cr = __ldg((const int4*)coords + i);   // [b, x, y, z]
        lmin0 = min(lmin0, cr.y); lmax0 = max(lmax0, cr.y);
        lmin1 = min(lmin1, cr.z); lmax1 = max(lmax1, cr.z);
        lmin2 = min(lmin2, cr.w); lmax2 = max(lmax2, cr.w);
    }
    lmin0 = __reduce_min_sync(0xffffffffu, lmin0);
    lmin1 = __reduce_min_sync(0xffffffffu, lmin1);
    lmin2 = __reduce_min_sync(0xffffffffu, lmin2);
    lmax0 = __reduce_max_sync(0xffffffffu, lmax0);
    lmax1 = __reduce_max_sync(0xffffffffu, lmax1);
    lmax2 = __reduce_max_sync(0xffffffffu, lmax2);
    if ((tid & 31) == 0) {
        atomicMin(&smin[0], lmin0); atomicMax(&smax[0], lmax0);
        atomicMin(&smin[1], lmin1); atomicMax(&smax[1], lmax1);
        atomicMin(&smin[2], lmin2); atomicMax(&smax[2], lmax2);
    }
    __syncthreads();
    if (tid < 3) { atomicMin(&g_bmin[tid], smin[tid]); atomicMax(&g_bmax[tid], smax[tid]); }
}

__device__ __forceinline__ float eluf(float x) { return x > 0.0f ? x : (__expf(x) - 1.0f); }

__device__ __forceinline__ void ffma2(ull& a, ull f, ull w) {
    asm("fma.rn.f32x2 %0, %1, %2, %0;" : "+l"(a) : "l"(f), "l"(w));
}
__device__ __forceinline__ float2 unpk(ull a) {
    float2 r; asm("mov.b64 {%0,%1}, %2;" : "=f"(r.x), "=f"(r.y) : "l"(a)); return r;
}
__device__ __forceinline__ ull pk2(float x, float y) {
    ull r; asm("mov.b64 %0, {%1,%2};" : "=l"(r) : "f"(x), "f"(y)); return r;
}

// [128 pts x 64 k] (k-major, optionally swizzled) x dup-weights [64 k][128] ->
// acc[col 0..7][pt-pair 0..1] packed f32x2. tx: point group, ty: col group.
template<bool SWZ>
__device__ __forceinline__ void gemm64_f2(const float* __restrict__ inp,
                                          const float* __restrict__ wd,
                                          int tx, int ty, ull acc[16]) {
#pragma unroll
    for (int i = 0; i < 16; i++) acc[i] = 0ull;
    int f_off[8];
#pragma unroll
    for (int j = 0; j < 8; j++) f_off[j] = SWZ ? ((tx * 4) ^ (j << 2)) : (tx * 4);
    const float* wp = wd + ty * 16;
    for (int k8 = 0; k8 < 8; k8++) {
#pragma unroll
        for (int j = 0; j < 8; j++) {
            int k = k8 * 8 + j;
            ulonglong2 f   = *(const ulonglong2*)(inp + k * TILE + f_off[j]);
            ulonglong2 w01 = *(const ulonglong2*)(wp + k * TILE);
            ulonglong2 w23 = *(const ulonglong2*)(wp + k * TILE + 4);
            ulonglong2 w45 = *(const ulonglong2*)(wp + k * TILE + 8);
            ulonglong2 w67 = *(const ulonglong2*)(wp + k * TILE + 12);
            ffma2(acc[0],  f.x, w01.x); ffma2(acc[1],  f.y, w01.x);
            ffma2(acc[2],  f.x, w01.y); ffma2(acc[3],  f.y, w01.y);
            ffma2(acc[4],  f.x, w23.x); ffma2(acc[5],  f.y, w23.x);
            ffma2(acc[6],  f.x, w23.y); ffma2(acc[7],  f.y, w23.y);
            ffma2(acc[8],  f.x, w45.x); ffma2(acc[9],  f.y, w45.x);
            ffma2(acc[10], f.x, w45.y); ffma2(acc[11], f.y, w45.y);
            ffma2(acc[12], f.x, w67.x); ffma2(acc[13], f.y, w67.x);
            ffma2(acc[14], f.x, w67.y); ffma2(acc[15], f.y, w67.y);
        }
    }
}

__global__ __launch_bounds__(THREADS, 2)
void k_main(const int* __restrict__ coords, const float* __restrict__ feats,
            const float* __restrict__ W_sem, const float* __restrict__ b_sem,
            const float* __restrict__ W_o1, const float* __restrict__ g_o1,
            const float* __restrict__ b_o1, const float* __restrict__ W_o2,
            const float* __restrict__ g_o2, const float* __restrict__ b_o2,
            const float* __restrict__ W_o3, const float* __restrict__ W_ci,
            const float* __restrict__ g_ci, const float* __restrict__ b_ci,
            const float* __restrict__ W_ctr, const float* __restrict__ W_reg,
            const float* __restrict__ W_cls, const float* __restrict__ b_cls,
            const float* __restrict__ scales, float* __restrict__ out)
{
    extern __shared__ float sm[];
    float* s_feats = sm + SF_OFF;
    float* s_stage = sm + SSTG_OFF;
    float* s_Wd    = sm + SW_OFF;
    float* s_Wh    = sm + SWH_OFF;
    float* s_out   = sm + SOUT_OFF;
    unsigned* s_mask = (unsigned*)(sm + SMASK_OFF);
    unsigned* s_orv  = s_mask + TILE;

    const int tid = threadIdx.x;
    const int tx = tid & 31, ty = tid >> 5;
    const int n0 = blockIdx.x * TILE;

    // ---- P0a: coalesced load feats -> n-major staging [128][68];
    //           duplicate W_sem into s_Wd [64][36]; zero mask ----
    if (tid < TILE) s_mask[tid] = 0u;
#pragma unroll
    for (int it = 0; it < 8; it++) {
        int i = it * THREADS + tid;
        int n = i >> 4, c4 = i & 15;
        float4 v = __ldg((const float4*)(feats + (size_t)(n0 + n) * CF) + c4);
        *(float4*)(s_stage + n * 68 + c4 * 4) = v;
    }
    for (int i = tid; i < CF * NCLS; i += THREADS) {
        float w = __ldg(W_sem + i);
        int k = i / NCLS, c = i % NCLS;
        s_Wd[k * 36 + 2 * c] = w; s_Wd[k * 36 + 2 * c + 1] = w;
    }
    __syncthreads();

    // ---- P0b: transpose staging -> swizzled k-major s_feats ----
    {
        int l = tx, w = ty;
#pragma unroll
        for (int it = 0; it < 8; it++) {
            int k = l + ((it & 1) << 5);
            int g = w + ((it >> 1) << 3);
            float4 v;
            v.x = s_stage[(4 * g + 0) * 68 + k];
            v.y = s_stage[(4 * g + 1) * 68 + k];
            v.z = s_stage[(4 * g + 2) * 68 + k];
            v.w = s_stage[(4 * g + 3) * 68 + k];
            *(float4*)(s_feats + k * TILE + ((4 * g) ^ ((k & 7) << 2))) = v;
        }
    }
    __syncthreads();

    // ---- P1: semantic scores (packed) -> mask bitmask ----
    {
        int c0 = ty, c1 = ty + 8, c2 = ty + 16;      // c2 valid only for ty<2
        bool has2 = (c2 < NCLS);
        ull a0p[2], a1p[2], a2p[2];
        { float b0 = __ldg(b_sem + c0); a0p[0] = a0p[1] = pk2(b0, b0); }
        { float b1 = __ldg(b_sem + c1); a1p[0] = a1p[1] = pk2(b1, b1); }
        { float b2 = has2 ? __ldg(b_sem + c2) : 0.f; a2p[0] = a2p[1] = pk2(b2, b2); }
        int f_off[8];
#pragma unroll
        for (int j = 0; j < 8; j++) f_off[j] = (tx * 4) ^ (j << 2);
        for (int k8 = 0; k8 < 8; k8++) {
#pragma unroll
            for (int j = 0; j < 8; j++) {
                int k = k8 * 8 + j;
                ulonglong2 f = *(const ulonglong2*)(s_feats + k * TILE + f_off[j]);
                ull w0 = *(const ull*)(s_Wd + k * 36 + 2 * c0);
                ull w1 = *(const ull*)(s_Wd + k * 36 + 2 * c1);
                ffma2(a0p[0], f.x, w0); ffma2(a0p[1], f.y, w0);
                ffma2(a1p[0], f.x, w1); ffma2(a1p[1], f.y, w1);
                if (has2) {
                    ull w2 = *(const ull*)(s_Wd + k * 36 + 2 * c2);
                    ffma2(a2p[0], f.x, w2); ffma2(a2p[1], f.y, w2);
                }
            }
        }
#pragma unroll
        for (int p = 0; p < 2; p++) {
            float2 v0 = unpk(a0p[p]), v1 = unpk(a1p[p]), v2 = unpk(a2p[p]);
            int nb = tx * 4 + p * 2;
            if (v0.x > SEM_LOGIT) atomicOr(&s_mask[nb + 0], 1u << c0);
            if (v0.y > SEM_LOGIT) atomicOr(&s_mask[nb + 1], 1u << c0);
            if (v1.x > SEM_LOGIT) atomicOr(&s_mask[nb + 0], 1u << c1);
            if (v1.y > SEM_LOGIT) atomicOr(&s_mask[nb + 1], 1u << c1);
            if (has2) {
                if (v2.x > SEM_LOGIT) atomicOr(&s_mask[nb + 0], 1u << c2);
                if (v2.y > SEM_LOGIT) atomicOr(&s_mask[nb + 1], 1u << c2);
            }
        }
    }
    __syncthreads();
    if (tid < 32) {
        unsigned o = 0;
        for (int j = tid; j < TILE; j += 32) o |= s_mask[j];
        o = __reduce_or_sync(0xffffffffu, o);
        if (tid == 0) *s_orv = o;
    }
    // duplicate W_o1 into s_Wd [64][128]
#pragma unroll
    for (int it = 0; it < 4; it++) {
        int i = it * THREADS + tid;
        float4 v = __ldg((const float4*)W_o1 + i);
        int k = i >> 4, c4 = i & 15;
        *(float4*)(s_Wd + k * TILE + c4 * 8)     = make_float4(v.x, v.x, v.y, v.y);
        *(float4*)(s_Wd + k * TILE + c4 * 8 + 4) = make_float4(v.z, v.z, v.w, v.w);
    }
    __syncthreads();

    // ---- P2: offset MLP layer1 ----
    {
        ull acc[16];
        gemm64_f2<true>(s_feats, s_Wd, tx, ty, acc);
#pragma unroll
        for (int eo = 0; eo < 8; eo++) {
            int e = ty * 8 + eo;
            float g = __ldg(g_o1 + e), b = __ldg(b_o1 + e);
            float2 v0 = unpk(acc[eo * 2]), v1 = unpk(acc[eo * 2 + 1]);
            float4 o;
            o.x = eluf(fmaf(v0.x, g, b));
            o.y = eluf(fmaf(v0.y, g, b));
            o.z = eluf(fmaf(v1.x, g, b));
            o.w = eluf(fmaf(v1.y, g, b));
            *(float4*)(s_stage + e * TILE + tx * 4) = o;
        }
    }
    __syncthreads();
#pragma unroll
    for (int it = 0; it < 4; it++) {
        int i = it * THREADS + tid;
        float4 v = __ldg((const float4*)W_o2 + i);
        int k = i >> 4, c4 = i & 15;
        *(float4*)(s_Wd + k * TILE + c4 * 8)     = make_float4(v.x, v.x, v.y, v.y);
        *(float4*)(s_Wd + k * TILE + c4 * 8 + 4) = make_float4(v.z, v.z, v.w, v.w);
    }
    __syncthreads();
    // layer2 (in-place on s_stage: compute fully, sync, then write)
    {
        ull acc[16];
        gemm64_f2<false>(s_stage, s_Wd, tx, ty, acc);
        __syncthreads();
#pragma unroll
        for (int eo = 0; eo < 8; eo++) {
            int e = ty * 8 + eo;
            float g = __ldg(g_o2 + e), b = __ldg(b_o2 + e);
            float2 v0 = unpk(acc[eo * 2]), v1 = unpk(acc[eo * 2 + 1]);
            float4 o;
            o.x = eluf(fmaf(v0.x, g, b));
            o.y = eluf(fmaf(v0.y, g, b));
            o.z = eluf(fmaf(v1.x, g, b));
            o.w = eluf(fmaf(v1.y, g, b));
            *(float4*)(s_stage + e * TILE + tx * 4) = o;
        }
    }
    __syncthreads();
    // layer3: offset (3 cols) + voted clip + store
    for (int idx = tid; idx < TILE * 3; idx += THREADS) {
        int n = idx & (TILE - 1), r = idx >> 7;
        float acc = 0.0f;
#pragma unroll 8
        for (int k = 0; k < CF; k++)
            acc = fmaf(s_stage[k * TILE + n], __ldg(W_o3 + k * 3 + r), acc);
        float xyz = (float)__ldg(coords + (size_t)(n0 + n) * 4 + 1 + r);
        float mnb = (float)(g_bmin[r] - 1) * VOXEL;
        float mxb = (float)(g_bmax[r] + 1) * VOXEL;
        float v = fminf(fmaxf(fmaf(xyz, VOXEL, acc), mnb), mxb);
        out[OUT_VOFF + (size_t)(n0 + n) * 3 + r] = v;
    }

    const unsigned orv = *s_orv;   // written 3+ syncs ago, visible

    // ---- P3: per-class loop ----
    for (int c = 0; c < NCLS; c++) {
        float* outc = out + ((size_t)c * NPTS + n0) * 8;
        if (!((orv >> c) & 1u)) {
            // whole tile masked: feat_c == 0 -> ctr=0, reg=exp(0)=1, cls=b_cls
            float bc = __ldg(b_cls + c);
            int n = tid >> 1, h = tid & 1;
            float4 v = h ? make_float4(1.0f, 1.0f, 1.0f, bc)
                         : make_float4(0.0f, 1.0f, 1.0f, 1.0f);
            ((float4*)(outc + n * 8))[h] = v;
            continue;   // uniform branch (orv is block-uniform)
        }
        __syncthreads();   // protect s_Wd / s_stage / s_out reuse
        const float* Wc = W_ci + (size_t)c * CF * CF;
#pragma unroll
        for (int it = 0; it < 4; it++) {
            int i = it * THREADS + tid;
            float4 v = __ldg((const float4*)Wc + i);
            int k = i >> 4, c4 = i & 15;
            *(float4*)(s_Wd + k * TILE + c4 * 8)     = make_float4(v.x, v.x, v.y, v.y);
            *(float4*)(s_Wd + k * TILE + c4 * 8 + 4) = make_float4(v.z, v.z, v.w, v.w);
        }
        for (int i = tid; i < CF * 8; i += THREADS) {
            int k = i >> 3, j = i & 7;
            float w;
            if (j == 0)      w = __ldg(W_ctr + k);
            else if (j < 7)  w = __ldg(W_reg + k * 6 + (j - 1));
            else             w = __ldg(W_cls + k * NCLS + c);
            s_Wh[i] = w;
        }
        __syncthreads();
        // branch GEMM + BN + ELU + mask, staged into s_stage (k-major, no swz)
        {
            ull acc[16];
            gemm64_f2<true>(s_feats, s_Wd, tx, ty, acc);
            float m0 = (float)((s_mask[tx * 4 + 0] >> c) & 1u);
            float m1 = (float)((s_mask[tx * 4 + 1] >> c) & 1u);
            float m2 = (float)((s_mask[tx * 4 + 2] >> c) & 1u);
            float m3 = (float)((s_mask[tx * 4 + 3] >> c) & 1u);
#pragma unroll
            for (int eo = 0; eo < 8; eo++) {
                int e = ty * 8 + eo;
                float g = __ldg(g_ci + c * CF + e), b = __ldg(b_ci + c * CF + e);
                float2 v0 = unpk(acc[eo * 2]), v1 = unpk(acc[eo * 2 + 1]);
                float4 o;
                o.x = eluf(fmaf(v0.x, g, b)) * m0;
                o.y = eluf(fmaf(v0.y, g, b)) * m1;
                o.z = eluf(fmaf(v1.x, g, b)) * m2;
                o.w = eluf(fmaf(v1.y, g, b)) * m3;
                *(float4*)(s_stage + e * TILE + tx * 4) = o;
            }
        }
        __syncthreads();
        // head GEMM: 8 output cols, ty = output col
        {
            float a0 = 0.f, a1 = 0.f, a2 = 0.f, a3 = 0.f;
#pragma unroll 8
            for (int k = 0; k < CF; k++) {
                float4 f = *(const float4*)(s_stage + k * TILE + tx * 4);
                float w = s_Wh[k * 8 + ty];
                a0 = fmaf(f.x, w, a0); a1 = fmaf(f.y, w, a1);
                a2 = fmaf(f.z, w, a2); a3 = fmaf(f.w, w, a3);
            }
            float sc = __ldg(scales + c), bc = __ldg(b_cls + c);
            if (ty >= 1 && ty <= 6) {
                a0 = __expf(a0 * sc); a1 = __expf(a1 * sc);
                a2 = __expf(a2 * sc); a3 = __expf(a3 * sc);
            } else if (ty == 7) {
                a0 += bc; a1 += bc; a2 += bc; a3 += bc;
            }
            s_out[(tx * 4 + 0) * 9 + ty] = a0;
            s_out[(tx * 4 + 1) * 9 + ty] = a1;
            s_out[(tx * 4 + 2) * 9 + ty] = a2;
            s_out[(tx * 4 + 3) * 9 + ty] = a3;
        }
        __syncthreads();
        {
            int n = tid >> 1, h = tid & 1;
            float4 v;
            v.x = s_out[n * 9 + h * 4 + 0];
            v.y = s_out[n * 9 + h * 4 + 1];
            v.z = s_out[n * 9 + h * 4 + 2];
            v.w = s_out[n * 9 + h * 4 + 3];
            ((float4*)(outc + n * 8))[h] = v;
        }
    }
}

extern "C" void kernel_launch(void* const* d_in, const int* in_sizes, int n_in,
                              void* d_out, int out_size) {
    const int*   coords = (const int*)d_in[0];
    const float* feats  = (const float*)d_in[1];
    const float* W_sem  = (const float*)d_in[2];
    const float* b_sem  = (const float*)d_in[3];
    const float* W_o1   = (const float*)d_in[4];
    const float* g_o1   = (const float*)d_in[5];
    const float* b_o1   = (const float*)d_in[6];
    const float* W_o2   = (const float*)d_in[7];
    const float* g_o2   = (const float*)d_in[8];
    const float* b_o2   = (const float*)d_in[9];
    const float* W_o3   = (const float*)d_in[10];
    const float* W_ci   = (const float*)d_in[11];
    const float* g_ci   = (const float*)d_in[12];
    const float* b_ci   = (const float*)d_in[13];
    const float* W_ctr  = (const float*)d_in[14];
    const float* W_reg  = (const float*)d_in[15];
    const float* W_cls  = (const float*)d_in[16];
    const float* b_cls  = (const float*)d_in[17];
    const float* scales = (const float*)d_in[18];
    float* out = (float*)d_out;

    cudaFuncSetAttribute(k_main, cudaFuncAttributeMaxDynamicSharedMemorySize, SMEM_BYTES);
    k_bounds<<<264, 256>>>(coords);
    k_main<<<NTILES, THREADS, SMEM_BYTES>>>(coords, feats, W_sem, b_sem,
        W_o1, g_o1, b_o1, W_o2, g_o2, b_o2, W_o3, W_ci, g_ci, b_ci,
        W_ctr, W_reg, W_cls, b_cls, scales, out);
}

// round 4
// speedup vs baseline: 2.4224x; 1.7328x over previous
#include <cuda_runtime.h>
#include <cuda_bf16.h>
#include <math.h>

#define NPTS   131072
#define CF     64
#define NCLS   18
#define TILE   128
#define NTILES (NPTS / TILE)
#define VOXEL  0.04f
#define SEM_LOGIT (-1.7346010553881064f)
#define OUT_VOFF ((size_t)NCLS * NPTS * 8)
#define WS     72   // padded k-stride (elements) for weight images and s_h

// ---- pre-transposed bf16 weight images: [n][k] with k contiguous, padded ----
__device__ __nv_bfloat16 W1T[64 * WS];
__device__ __nv_bfloat16 W2T[64 * WS];
__device__ __nv_bfloat16 WSEMT[32 * WS];
__device__ __nv_bfloat16 WCIT[NCLS][64 * WS];
__device__ float HEADW[NCLS][64][8];   // [c][e][{ctr,reg0..5,cls}]

__device__ int g_bmin[3] = {0x7fffffff, 0x7fffffff, 0x7fffffff};
__device__ int g_bmax[3] = {(int)0x80000000, (int)0x80000000, (int)0x80000000};

__global__ void k_prep(const float* __restrict__ W_sem, const float* __restrict__ W_o1,
                       const float* __restrict__ W_o2, const float* __restrict__ W_ci,
                       const float* __restrict__ W_ctr, const float* __restrict__ W_reg,
                       const float* __restrict__ W_cls) {
    int i0 = blockIdx.x * blockDim.x + threadIdx.x;
    int stride = gridDim.x * blockDim.x;
    for (int t = i0; t < 64 * WS; t += stride) {
        int n = t / WS, k = t % WS;
        W1T[t] = __float2bfloat16_rn(k < 64 ? __ldg(W_o1 + k * 64 + n) : 0.0f);
        W2T[t] = __float2bfloat16_rn(k < 64 ? __ldg(W_o2 + k * 64 + n) : 0.0f);
    }
    for (int t = i0; t < 32 * WS; t += stride) {
        int n = t / WS, k = t % WS;
        WSEMT[t] = __float2bfloat16_rn((n < NCLS && k < 64) ? __ldg(W_sem + k * NCLS + n) : 0.0f);
    }
    for (int t = i0; t < NCLS * 64 * WS; t += stride) {
        int c = t / (64 * WS), r = t % (64 * WS);
        int n = r / WS, k = r % WS;
        WCIT[c][r] = __float2bfloat16_rn(k < 64 ? __ldg(W_ci + (size_t)c * 4096 + k * 64 + n) : 0.0f);
    }
    for (int t = i0; t < NCLS * 64 * 8; t += stride) {
        int c = t >> 9, r = t & 511;
        int e = r >> 3, j = r & 7;
        float v;
        if (j == 0)      v = __ldg(W_ctr + e);
        else if (j < 7)  v = __ldg(W_reg + e * 6 + (j - 1));
        else             v = __ldg(W_cls + e * NCLS + c);
        HEADW[c][e][j] = v;
    }
}

__global__ void k_bounds(const int* __restrict__ coords) {
    __shared__ int smin[3], smax[3];
    int tid = threadIdx.x;
    if (tid < 3) { smin[tid] = 0x7fffffff; smax[tid] = (int)0x80000000; }
    __syncthreads();
    int l0 = 0x7fffffff, l1 = 0x7fffffff, l2 = 0x7fffffff;
    int h0 = (int)0x80000000, h1 = (int)0x80000000, h2 = (int)0x80000000;
    for (int i = blockIdx.x * blockDim.x + tid; i < NPTS; i += gridDim.x * blockDim.x) {
        int4 cr = __ldg((const int4*)coords + i);
        l0 = min(l0, cr.y); h0 = max(h0, cr.y);
        l1 = min(l1, cr.z); h1 = max(h1, cr.z);
        l2 = min(l2, cr.w); h2 = max(h2, cr.w);
    }
    l0 = __reduce_min_sync(0xffffffffu, l0); h0 = __reduce_max_sync(0xffffffffu, h0);
    l1 = __reduce_min_sync(0xffffffffu, l1); h1 = __reduce_max_sync(0xffffffffu, h1);
    l2 = __reduce_min_sync(0xffffffffu, l2); h2 = __reduce_max_sync(0xffffffffu, h2);
    if ((tid & 31) == 0) {
        atomicMin(&smin[0], l0); atomicMax(&smax[0], h0);
        atomicMin(&smin[1], l1); atomicMax(&smax[1], h1);
        atomicMin(&smin[2], l2); atomicMax(&smax[2], h2);
    }
    __syncthreads();
    if (tid < 3) { atomicMin(&g_bmin[tid], smin[tid]); atomicMax(&g_bmax[tid], smax[tid]); }
}

__device__ __forceinline__ float eluf(float x) { return x > 0.0f ? x : (__expf(x) - 1.0f); }

__device__ __forceinline__ unsigned packbf(float lo, float hi) {
    __nv_bfloat162 p = __floats2bfloat162_rn(lo, hi);
    return *(unsigned*)&p;
}

// D(16x8,f32) += A(16x16,bf16 row) x B(16x8,bf16 col)
__device__ __forceinline__ void mma16816(float* c, const unsigned* a, unsigned b0, unsigned b1) {
    asm volatile("mma.sync.aligned.m16n8k16.row.col.f32.bf16.bf16.f32 "
                 "{%0,%1,%2,%3}, {%4,%5,%6,%7}, {%8,%9}, {%0,%1,%2,%3};"
                 : "+f"(c[0]), "+f"(c[1]), "+f"(c[2]), "+f"(c[3])
                 : "r"(a[0]), "r"(a[1]), "r"(a[2]), "r"(a[3]), "r"(b0), "r"(b1));
}

// A fragment from fp32 global rows (row-major, k contiguous)
__device__ __forceinline__ void ldfragA(const float* b0, const float* b1, int kb, unsigned* a) {
    float2 f0 = __ldg((const float2*)(b0 + kb));
    float2 f1 = __ldg((const float2*)(b1 + kb));
    float2 f2 = __ldg((const float2*)(b0 + kb + 8));
    float2 f3 = __ldg((const float2*)(b1 + kb + 8));
    a[0] = packbf(f0.x, f0.y); a[1] = packbf(f1.x, f1.y);
    a[2] = packbf(f2.x, f2.y); a[3] = packbf(f3.x, f3.y);
}

__global__ __launch_bounds__(256, 3)
void k_main(const int* __restrict__ coords, const float* __restrict__ feats,
            const float* __restrict__ b_sem,
            const float* __restrict__ g_o1, const float* __restrict__ b_o1,
            const float* __restrict__ g_o2, const float* __restrict__ b_o2,
            const float* __restrict__ W_o3,
            const float* __restrict__ g_ci, const float* __restrict__ b_ci,
            const float* __restrict__ b_cls, const float* __restrict__ scales,
            float* __restrict__ out)
{
    __shared__ __nv_bfloat16 s_h[TILE * WS];   // 18432 B
    __shared__ unsigned s_mask[TILE];
    __shared__ unsigned s_or[8];

    const int tid  = threadIdx.x;
    const int w    = tid >> 5;
    const int lane = tid & 31;
    const int g    = lane >> 2;
    const int t    = lane & 3;
    const int n0   = blockIdx.x * TILE;
    const int r0l  = w * 16 + g;      // local rows this thread covers
    const int r1l  = r0l + 8;

    // ---- A fragments straight from global fp32 feats ----
    unsigned af[4][4];
    {
        const float* fb0 = feats + (size_t)(n0 + r0l) * CF + 2 * t;
        const float* fb1 = feats + (size_t)(n0 + r1l) * CF + 2 * t;
#pragma unroll
        for (int ks = 0; ks < 4; ks++) ldfragA(fb0, fb1, ks * 16, af[ks]);
    }

    // ---- sem GEMM (N=24 covers 18 classes) -> mask bits ----
    unsigned m0 = 0, m1 = 0;
#pragma unroll
    for (int nb = 0; nb < 3; nb++) {
        float cs[4] = {0.f, 0.f, 0.f, 0.f};
        const __nv_bfloat16* wn = WSEMT + (nb * 8 + g) * WS + 2 * t;
#pragma unroll
        for (int ks = 0; ks < 4; ks++) {
            unsigned b0 = __ldg((const unsigned*)(wn + ks * 16));
            unsigned b1 = __ldg((const unsigned*)(wn + ks * 16 + 8));
            mma16816(cs, af[ks], b0, b1);
        }
        int e0 = nb * 8 + 2 * t, e1 = e0 + 1;
        if (e0 < NCLS) {
            float thr = SEM_LOGIT - __ldg(b_sem + e0);
            if (cs[0] > thr) m0 |= 1u << e0;
            if (cs[2] > thr) m1 |= 1u << e0;
        }
        if (e1 < NCLS) {
            float thr = SEM_LOGIT - __ldg(b_sem + e1);
            if (cs[1] > thr) m0 |= 1u << e1;
            if (cs[3] > thr) m1 |= 1u << e1;
        }
    }
    m0 |= __shfl_xor_sync(0xffffffffu, m0, 1); m0 |= __shfl_xor_sync(0xffffffffu, m0, 2);
    m1 |= __shfl_xor_sync(0xffffffffu, m1, 1); m1 |= __shfl_xor_sync(0xffffffffu, m1, 2);
    if (t == 0) { s_mask[r0l] = m0; s_mask[r1l] = m1; }
    {
        unsigned wor = __reduce_or_sync(0xffffffffu, m0 | m1);
        if (lane == 0) s_or[w] = wor;
    }

    // ---- l1 GEMM ----
    {
        float c1[8][4];
#pragma unroll
        for (int nb = 0; nb < 8; nb++) { c1[nb][0] = c1[nb][1] = c1[nb][2] = c1[nb][3] = 0.f; }
#pragma unroll
        for (int nb = 0; nb < 8; nb++) {
            const __nv_bfloat16* wn = W1T + (nb * 8 + g) * WS + 2 * t;
#pragma unroll
            for (int ks = 0; ks < 4; ks++) {
                unsigned b0 = __ldg((const unsigned*)(wn + ks * 16));
                unsigned b1 = __ldg((const unsigned*)(wn + ks * 16 + 8));
                mma16816(c1[nb], af[ks], b0, b1);
            }
        }
        // BN + ELU -> bf16 h in smem (conflict-free: word = 4g + 4nb + t mod 32)
#pragma unroll
        for (int nb = 0; nb < 8; nb++) {
            int e0 = nb * 8 + 2 * t, e1 = e0 + 1;
            float ga = __ldg(g_o1 + e0), ba = __ldg(b_o1 + e0);
            float gb = __ldg(g_o1 + e1), bb = __ldg(b_o1 + e1);
            *(unsigned*)&s_h[r0l * WS + e0] =
                packbf(eluf(fmaf(c1[nb][0], ga, ba)), eluf(fmaf(c1[nb][1], gb, bb)));
            *(unsigned*)&s_h[r1l * WS + e0] =
                packbf(eluf(fmaf(c1[nb][2], ga, ba)), eluf(fmaf(c1[nb][3], gb, bb)));
        }
    }
    __syncthreads();
    const unsigned orv = s_or[0] | s_or[1] | s_or[2] | s_or[3] |
                         s_or[4] | s_or[5] | s_or[6] | s_or[7];

    // ---- l2 GEMM (A = h from smem) + BN/ELU + l3 dot + voted ----
    {
        unsigned a2[4][4];
#pragma unroll
        for (int ks = 0; ks < 4; ks++) {
            int kb = ks * 16 + 2 * t;
            a2[ks][0] = *(const unsigned*)&s_h[r0l * WS + kb];
            a2[ks][1] = *(const unsigned*)&s_h[r1l * WS + kb];
            a2[ks][2] = *(const unsigned*)&s_h[r0l * WS + kb + 8];
            a2[ks][3] = *(const unsigned*)&s_h[r1l * WS + kb + 8];
        }
        float o0x = 0.f, o0y = 0.f, o0z = 0.f, o1x = 0.f, o1y = 0.f, o1z = 0.f;
#pragma unroll
        for (int nb = 0; nb < 8; nb++) {
            float c2[4] = {0.f, 0.f, 0.f, 0.f};
            const __nv_bfloat16* wn = W2T + (nb * 8 + g) * WS + 2 * t;
#pragma unroll
            for (int ks = 0; ks < 4; ks++) {
                unsigned b0 = __ldg((const unsigned*)(wn + ks * 16));
                unsigned b1 = __ldg((const unsigned*)(wn + ks * 16 + 8));
                mma16816(c2, a2[ks], b0, b1);
            }
            int e0 = nb * 8 + 2 * t, e1 = e0 + 1;
            float ga = __ldg(g_o2 + e0), ba = __ldg(b_o2 + e0);
            float gb = __ldg(g_o2 + e1), bb = __ldg(b_o2 + e1);
            float h00 = eluf(fmaf(c2[0], ga, ba)), h01 = eluf(fmaf(c2[1], gb, bb));
            float h10 = eluf(fmaf(c2[2], ga, ba)), h11 = eluf(fmaf(c2[3], gb, bb));
            float w0x = __ldg(W_o3 + e0 * 3),     w1x = __ldg(W_o3 + e1 * 3);
            float w0y = __ldg(W_o3 + e0 * 3 + 1), w1y = __ldg(W_o3 + e1 * 3 + 1);
            float w0z = __ldg(W_o3 + e0 * 3 + 2), w1z = __ldg(W_o3 + e1 * 3 + 2);
            o0x = fmaf(h00, w0x, fmaf(h01, w1x, o0x));
            o0y = fmaf(h00, w0y, fmaf(h01, w1y, o0y));
            o0z = fmaf(h00, w0z, fmaf(h01, w1z, o0z));
            o1x = fmaf(h10, w0x, fmaf(h11, w1x, o1x));
            o1y = fmaf(h10, w0y, fmaf(h11, w1y, o1y));
            o1z = fmaf(h10, w0z, fmaf(h11, w1z, o1z));
        }
#pragma unroll
        for (int s = 1; s <= 2; s <<= 1) {
            o0x += __shfl_xor_sync(0xffffffffu, o0x, s);
            o0y += __shfl_xor_sync(0xffffffffu, o0y, s);
            o0z += __shfl_xor_sync(0xffffffffu, o0z, s);
            o1x += __shfl_xor_sync(0xffffffffu, o1x, s);
            o1y += __shfl_xor_sync(0xffffffffu, o1y, s);
            o1z += __shfl_xor_sync(0xffffffffu, o1z, s);
        }
        if (t == 0) {
            float mn0 = (float)(g_bmin[0] - 1) * VOXEL, mx0 = (float)(g_bmax[0] + 1) * VOXEL;
            float mn1 = (float)(g_bmin[1] - 1) * VOXEL, mx1 = (float)(g_bmax[1] + 1) * VOXEL;
            float mn2 = (float)(g_bmin[2] - 1) * VOXEL, mx2 = (float)(g_bmax[2] + 1) * VOXEL;
            int4 c0 = __ldg((const int4*)coords + (n0 + r0l));
            int4 c1 = __ldg((const int4*)coords + (n0 + r1l));
            float* v0 = out + OUT_VOFF + (size_t)(n0 + r0l) * 3;
            float* v1 = out + OUT_VOFF + (size_t)(n0 + r1l) * 3;
            v0[0] = fminf(fmaxf(fmaf((float)c0.y, VOXEL, o0x), mn0), mx0);
            v0[1] = fminf(fmaxf(fmaf((float)c0.z, VOXEL, o0y), mn1), mx1);
            v0[2] = fminf(fmaxf(fmaf((float)c0.w, VOXEL, o0z), mn2), mx2);
            v1[0] = fminf(fmaxf(fmaf((float)c1.y, VOXEL, o1x), mn0), mx0);
            v1[1] = fminf(fmaxf(fmaf((float)c1.z, VOXEL, o1y), mn1), mx1);
            v1[2] = fminf(fmaxf(fmaf((float)c1.w, VOXEL, o1z), mn2), mx2);
        }
    }

    // ---- per-class loop ----
    for (int c = 0; c < NCLS; c++) {
        if (!((orv >> c) & 1u)) {
            // whole tile masked for class c: feat_c == 0 exactly
            // -> ctr = 0, reg = exp(0) = 1, cls = b_cls[c]
            float bc = __ldg(b_cls + c);
            float4 v = (tid & 1) ? make_float4(1.0f, 1.0f, 1.0f, bc)
                                 : make_float4(0.0f, 1.0f, 1.0f, 1.0f);
            ((float4*)(out + ((size_t)c * NPTS + n0) * 8))[tid] = v;
            continue;   // uniform branch (orv is block-uniform)
        }
        // ---- slow path (fully correct; taken only if some point is unmasked) ----
        float cc[8][4];
#pragma unroll
        for (int nb = 0; nb < 8; nb++) { cc[nb][0] = cc[nb][1] = cc[nb][2] = cc[nb][3] = 0.f; }
#pragma unroll
        for (int nb = 0; nb < 8; nb++) {
            const __nv_bfloat16* wn = WCIT[c] + (nb * 8 + g) * WS + 2 * t;
#pragma unroll
            for (int ks = 0; ks < 4; ks++) {
                unsigned b0 = __ldg((const unsigned*)(wn + ks * 16));
                unsigned b1 = __ldg((const unsigned*)(wn + ks * 16 + 8));
                mma16816(cc[nb], af[ks], b0, b1);
            }
        }
        float mk0 = (float)((s_mask[r0l] >> c) & 1u);
        float mk1 = (float)((s_mask[r1l] >> c) & 1u);
        float o0[8], o1[8];
#pragma unroll
        for (int j = 0; j < 8; j++) { o0[j] = 0.f; o1[j] = 0.f; }
#pragma unroll
        for (int nb = 0; nb < 8; nb++) {
            int e0 = nb * 8 + 2 * t, e1 = e0 + 1;
            float ga = __ldg(g_ci + c * CF + e0), ba = __ldg(b_ci + c * CF + e0);
            float gb = __ldg(g_ci + c * CF + e1), bb = __ldg(b_ci + c * CF + e1);
            float f00 = eluf(fmaf(cc[nb][0], ga, ba)) * mk0;
            float f01 = eluf(fmaf(cc[nb][1], gb, bb)) * mk0;
            float f10 = eluf(fmaf(cc[nb][2], ga, ba)) * mk1;
            float f11 = eluf(fmaf(cc[nb][3], gb, bb)) * mk1;
            const float* he0 = &HEADW[c][e0][0];
            const float* he1 = &HEADW[c][e1][0];
#pragma unroll
            for (int j = 0; j < 8; j++) {
                float w0 = __ldg(he0 + j), w1 = __ldg(he1 + j);
                o0[j] = fmaf(f00, w0, fmaf(f01, w1, o0[j]));
                o1[j] = fmaf(f10, w0, fmaf(f11, w1, o1[j]));
            }
        }
#pragma unroll
        for (int s = 1; s <= 2; s <<= 1) {
#pragma unroll
            for (int j = 0; j < 8; j++) {
                o0[j] += __shfl_xor_sync(0xffffffffu, o0[j], s);
                o1[j] += __shfl_xor_sync(0xffffffffu, o1[j], s);
            }
        }
        if (t == 0) {
            float sc = __ldg(scales + c), bc = __ldg(b_cls + c);
            float* p0 = out + ((size_t)c * NPTS + n0 + r0l) * 8;
            float* p1 = out + ((size_t)c * NPTS + n0 + r1l) * 8;
            *(float4*)(p0)     = make_float4(o0[0], __expf(o0[1] * sc), __expf(o0[2] * sc), __expf(o0[3] * sc));
            *(float4*)(p0 + 4) = make_float4(__expf(o0[4] * sc), __expf(o0[5] * sc), __expf(o0[6] * sc), o0[7] + bc);
            *(float4*)(p1)     = make_float4(o1[0], __expf(o1[1] * sc), __expf(o1[2] * sc), __expf(o1[3] * sc));
            *(float4*)(p1 + 4) = make_float4(__expf(o1[4] * sc), __expf(o1[5] * sc), __expf(o1[6] * sc), o1[7] + bc);
        }
    }
}

extern "C" void kernel_launch(void* const* d_in, const int* in_sizes, int n_in,
                              void* d_out, int out_size) {
    const int*   coords = (const int*)d_in[0];
    const float* feats  = (const float*)d_in[1];
    const float* W_sem  = (const float*)d_in[2];
    const float* b_sem  = (const float*)d_in[3];
    const float* W_o1   = (const float*)d_in[4];
    const float* g_o1   = (const float*)d_in[5];
    const float* b_o1   = (const float*)d_in[6];
    const float* W_o2   = (const float*)d_in[7];
    const float* g_o2   = (const float*)d_in[8];
    const float* b_o2   = (const float*)d_in[9];
    const float* W_o3   = (const float*)d_in[10];
    const float* W_ci   = (const float*)d_in[11];
    const float* g_ci   = (const float*)d_in[12];
    const float* b_ci   = (const float*)d_in[13];
    const float* W_ctr  = (const float*)d_in[14];
    const float* W_reg  = (const float*)d_in[15];
    const float* W_cls  = (const float*)d_in[16];
    const float* b_cls  = (const float*)d_in[17];
    const float* scales = (const float*)d_in[18];
    float* out = (float*)d_out;

    k_prep<<<64, 256>>>(W_sem, W_o1, W_o2, W_ci, W_ctr, W_reg, W_cls);
    k_bounds<<<264, 256>>>(coords);
    k_main<<<NTILES, 256>>>(coords, feats, b_sem, g_o1, b_o1, g_o2, b_o2,
                            W_o3, g_ci, b_ci, b_cls, scales, out);
}

// round 6
// speedup vs baseline: 2.8839x; 1.1905x over previous
#include <cuda_runtime.h>
#include <cuda_bf16.h>
#include <math.h>

#define NPTS   131072
#define CF     64
#define NCLS   18
#define TILE   128
#define NTILES (NPTS / TILE)
#define VOXEL  0.04f
#define SEM_LOGIT (-1.7346010553881064f)
#define OUT_VOFF ((size_t)NCLS * NPTS * 8)
#define WS     72   // padded k-stride (elements) for weight images

#define BND_BLKS 264
#define PRE_BLKS 248

// ---- pre-transposed bf16 weight images: [n][k] with k contiguous, padded ----
__device__ __nv_bfloat16 W1T[64 * WS];
__device__ __nv_bfloat16 W2T[64 * WS];
__device__ __nv_bfloat16 WSEMT[32 * WS];
__device__ __nv_bfloat16 WCIT[NCLS][64 * WS];
__device__ float HEADW[NCLS][64][8];   // [c][e][{ctr,reg0..5,cls}]

__device__ int g_bmin[3] = {0x7fffffff, 0x7fffffff, 0x7fffffff};
__device__ int g_bmax[3] = {(int)0x80000000, (int)0x80000000, (int)0x80000000};

__global__ void k_pre(const int* __restrict__ coords,
                      const float* __restrict__ W_sem, const float* __restrict__ W_o1,
                      const float* __restrict__ W_o2, const float* __restrict__ W_ci,
                      const float* __restrict__ W_ctr, const float* __restrict__ W_reg,
                      const float* __restrict__ W_cls) {
    int tid = threadIdx.x;
    if (blockIdx.x < BND_BLKS) {
        // ---- scene bounds ----
        __shared__ int smin[3], smax[3];
        if (tid < 3) { smin[tid] = 0x7fffffff; smax[tid] = (int)0x80000000; }
        __syncthreads();
        int l0 = 0x7fffffff, l1 = 0x7fffffff, l2 = 0x7fffffff;
        int h0 = (int)0x80000000, h1 = (int)0x80000000, h2 = (int)0x80000000;
        for (int i = blockIdx.x * 256 + tid; i < NPTS; i += BND_BLKS * 256) {
            int4 cr = __ldg((const int4*)coords + i);
            l0 = min(l0, cr.y); h0 = max(h0, cr.y);
            l1 = min(l1, cr.z); h1 = max(h1, cr.z);
            l2 = min(l2, cr.w); h2 = max(h2, cr.w);
        }
        l0 = __reduce_min_sync(0xffffffffu, l0); h0 = __reduce_max_sync(0xffffffffu, h0);
        l1 = __reduce_min_sync(0xffffffffu, l1); h1 = __reduce_max_sync(0xffffffffu, h1);
        l2 = __reduce_min_sync(0xffffffffu, l2); h2 = __reduce_max_sync(0xffffffffu, h2);
        if ((tid & 31) == 0) {
            atomicMin(&smin[0], l0); atomicMax(&smax[0], h0);
            atomicMin(&smin[1], l1); atomicMax(&smax[1], h1);
            atomicMin(&smin[2], l2); atomicMax(&smax[2], h2);
        }
        __syncthreads();
        if (tid < 3) { atomicMin(&g_bmin[tid], smin[tid]); atomicMax(&g_bmax[tid], smax[tid]); }
    } else {
        // ---- weight image prep ----
        int i0 = (blockIdx.x - BND_BLKS) * 256 + tid;
        int stride = PRE_BLKS * 256;
        for (int t = i0; t < 64 * WS; t += stride) {
            int n = t / WS, k = t % WS;
            W1T[t] = __float2bfloat16_rn(k < 64 ? __ldg(W_o1 + k * 64 + n) : 0.0f);
            W2T[t] = __float2bfloat16_rn(k < 64 ? __ldg(W_o2 + k * 64 + n) : 0.0f);
        }
        for (int t = i0; t < 32 * WS; t += stride) {
            int n = t / WS, k = t % WS;
            WSEMT[t] = __float2bfloat16_rn((n < NCLS && k < 64) ? __ldg(W_sem + k * NCLS + n) : 0.0f);
        }
        for (int t = i0; t < NCLS * 64 * WS; t += stride) {
            int c = t / (64 * WS), r = t % (64 * WS);
            int n = r / WS, k = r % WS;
            WCIT[c][r] = __float2bfloat16_rn(k < 64 ? __ldg(W_ci + (size_t)c * 4096 + k * 64 + n) : 0.0f);
        }
        for (int t = i0; t < NCLS * 64 * 8; t += stride) {
            int c = t >> 9, r = t & 511;
            int e = r >> 3, j = r & 7;
            float v;
            if (j == 0)      v = __ldg(W_ctr + e);
            else if (j < 7)  v = __ldg(W_reg + e * 6 + (j - 1));
            else             v = __ldg(W_cls + e * NCLS + c);
            HEADW[c][e][j] = v;
        }
    }
}

__device__ __forceinline__ float eluf(float x) { return x > 0.0f ? x : (__expf(x) - 1.0f); }

__device__ __forceinline__ unsigned packbf(float lo, float hi) {
    __nv_bfloat162 p = __floats2bfloat162_rn(lo, hi);
    return *(unsigned*)&p;
}

// D(16x8,f32) += A(16x16,bf16 row) x B(16x8,bf16 col)
__device__ __forceinline__ void mma16816(float* c, const unsigned* a, unsigned b0, unsigned b1) {
    asm volatile("mma.sync.aligned.m16n8k16.row.col.f32.bf16.bf16.f32 "
                 "{%0,%1,%2,%3}, {%4,%5,%6,%7}, {%8,%9}, {%0,%1,%2,%3};"
                 : "+f"(c[0]), "+f"(c[1]), "+f"(c[2]), "+f"(c[3])
                 : "r"(a[0]), "r"(a[1]), "r"(a[2]), "r"(a[3]), "r"(b0), "r"(b1));
}

// A fragment from fp32 global rows (row-major, k contiguous)
__device__ __forceinline__ void ldfragA(const float* b0, const float* b1, int kb, unsigned* a) {
    float2 f0 = __ldg((const float2*)(b0 + kb));
    float2 f1 = __ldg((const float2*)(b1 + kb));
    float2 f2 = __ldg((const float2*)(b0 + kb + 8));
    float2 f3 = __ldg((const float2*)(b1 + kb + 8));
    a[0] = packbf(f0.x, f0.y); a[1] = packbf(f1.x, f1.y);
    a[2] = packbf(f2.x, f2.y); a[3] = packbf(f3.x, f3.y);
}

__global__ __launch_bounds__(256, 3)
void k_main(const int* __restrict__ coords, const float* __restrict__ feats,
            const float* __restrict__ b_sem,
            const float* __restrict__ g_o1, const float* __restrict__ b_o1,
            const float* __restrict__ g_o2, const float* __restrict__ b_o2,
            const float* __restrict__ W_o3,
            const float* __restrict__ g_ci, const float* __restrict__ b_ci,
            const float* __restrict__ b_cls, const float* __restrict__ scales,
            float* __restrict__ out)
{
    const int tid  = threadIdx.x;
    const int w    = tid >> 5;
    const int lane = tid & 31;
    const int g    = lane >> 2;
    const int t    = lane & 3;
    const int n0   = blockIdx.x * TILE;
    const int r0l  = w * 16 + g;      // local rows this thread covers
    const int r1l  = r0l + 8;

    // ---- A fragments straight from global fp32 feats ----
    unsigned af[4][4];
    {
        const float* fb0 = feats + (size_t)(n0 + r0l) * CF + 2 * t;
        const float* fb1 = feats + (size_t)(n0 + r1l) * CF + 2 * t;
#pragma unroll
        for (int ks = 0; ks < 4; ks++) ldfragA(fb0, fb1, ks * 16, af[ks]);
    }

    // ---- sem GEMM (N=24 covers 18 classes) -> per-row mask bits (in regs) ----
    unsigned m0 = 0, m1 = 0;
#pragma unroll
    for (int nb = 0; nb < 3; nb++) {
        float cs[4] = {0.f, 0.f, 0.f, 0.f};
        const __nv_bfloat16* wn = WSEMT + (nb * 8 + g) * WS + 2 * t;
#pragma unroll
        for (int ks = 0; ks < 4; ks++) {
            unsigned b0 = __ldg((const unsigned*)(wn + ks * 16));
            unsigned b1 = __ldg((const unsigned*)(wn + ks * 16 + 8));
            mma16816(cs, af[ks], b0, b1);
        }
        int e0 = nb * 8 + 2 * t, e1 = e0 + 1;
        if (e0 < NCLS) {
            float thr = SEM_LOGIT - __ldg(b_sem + e0);
            if (cs[0] > thr) m0 |= 1u << e0;
            if (cs[2] > thr) m1 |= 1u << e0;
        }
        if (e1 < NCLS) {
            float thr = SEM_LOGIT - __ldg(b_sem + e1);
            if (cs[1] > thr) m0 |= 1u << e1;
            if (cs[3] > thr) m1 |= 1u << e1;
        }
    }
    // quad-OR: every thread gets full mask for its two rows
    m0 |= __shfl_xor_sync(0xffffffffu, m0, 1); m0 |= __shfl_xor_sync(0xffffffffu, m0, 2);
    m1 |= __shfl_xor_sync(0xffffffffu, m1, 1); m1 |= __shfl_xor_sync(0xffffffffu, m1, 2);
    // warp-level OR over this warp's 16 rows (fast/slow decision is warp-local)
    const unsigned orv = __reduce_or_sync(0xffffffffu, m0 | m1);

    // ---- l1 GEMM -> registers ----
    float c1[8][4];
#pragma unroll
    for (int nb = 0; nb < 8; nb++) { c1[nb][0] = c1[nb][1] = c1[nb][2] = c1[nb][3] = 0.f; }
#pragma unroll
    for (int nb = 0; nb < 8; nb++) {
        const __nv_bfloat16* wn = W1T + (nb * 8 + g) * WS + 2 * t;
#pragma unroll
        for (int ks = 0; ks < 4; ks++) {
            unsigned b0 = __ldg((const unsigned*)(wn + ks * 16));
            unsigned b1 = __ldg((const unsigned*)(wn + ks * 16 + 8));
            mma16816(c1[nb], af[ks], b0, b1);
        }
    }

    // ---- BN+ELU(l1) -> l2 A-fragments ENTIRELY IN REGISTERS ----
    // C-frag (row g, cols 2t,2t+1) == A-frag (row g, k 2t,2t+1): nb-pair (2ks,2ks+1) -> k-block ks
    unsigned a2[4][4];
#pragma unroll
    for (int ks = 0; ks < 4; ks++) {
        int nA = 2 * ks, nB = 2 * ks + 1;
        int eA0 = nA * 8 + 2 * t, eA1 = eA0 + 1;
        int eB0 = nB * 8 + 2 * t, eB1 = eB0 + 1;
        float gA0 = __ldg(g_o1 + eA0), bA0 = __ldg(b_o1 + eA0);
        float gA1 = __ldg(g_o1 + eA1), bA1 = __ldg(b_o1 + eA1);
        float gB0 = __ldg(g_o1 + eB0), bB0 = __ldg(b_o1 + eB0);
        float gB1 = __ldg(g_o1 + eB1), bB1 = __ldg(b_o1 + eB1);
        a2[ks][0] = packbf(eluf(fmaf(c1[nA][0], gA0, bA0)), eluf(fmaf(c1[nA][1], gA1, bA1)));
        a2[ks][1] = packbf(eluf(fmaf(c1[nA][2], gA0, bA0)), eluf(fmaf(c1[nA][3], gA1, bA1)));
        a2[ks][2] = packbf(eluf(fmaf(c1[nB][0], gB0, bB0)), eluf(fmaf(c1[nB][1], gB1, bB1)));
        a2[ks][3] = packbf(eluf(fmaf(c1[nB][2], gB0, bB0)), eluf(fmaf(c1[nB][3], gB1, bB1)));
    }

    // ---- l2 GEMM + BN/ELU + l3 dot + voted ----
    {
        float o0x = 0.f, o0y = 0.f, o0z = 0.f, o1x = 0.f, o1y = 0.f, o1z = 0.f;
#pragma unroll
        for (int nb = 0; nb < 8; nb++) {
            float c2[4] = {0.f, 0.f, 0.f, 0.f};
            const __nv_bfloat16* wn = W2T + (nb * 8 + g) * WS + 2 * t;
#pragma unroll
            for (int ks = 0; ks < 4; ks++) {
                unsigned b0 = __ldg((const unsigned*)(wn + ks * 16));
                unsigned b1 = __ldg((const unsigned*)(wn + ks * 16 + 8));
                mma16816(c2, a2[ks], b0, b1);
            }
            int e0 = nb * 8 + 2 * t, e1 = e0 + 1;
            float ga = __ldg(g_o2 + e0), ba = __ldg(b_o2 + e0);
            float gb = __ldg(g_o2 + e1), bb = __ldg(b_o2 + e1);
            float h00 = eluf(fmaf(c2[0], ga, ba)), h01 = eluf(fmaf(c2[1], gb, bb));
            float h10 = eluf(fmaf(c2[2], ga, ba)), h11 = eluf(fmaf(c2[3], gb, bb));
            float w0x = __ldg(W_o3 + e0 * 3),     w1x = __ldg(W_o3 + e1 * 3);
            float w0y = __ldg(W_o3 + e0 * 3 + 1), w1y = __ldg(W_o3 + e1 * 3 + 1);
            float w0z = __ldg(W_o3 + e0 * 3 + 2), w1z = __ldg(W_o3 + e1 * 3 + 2);
            o0x = fmaf(h00, w0x, fmaf(h01, w1x, o0x));
            o0y = fmaf(h00, w0y, fmaf(h01, w1y, o0y));
            o0z = fmaf(h00, w0z, fmaf(h01, w1z, o0z));
            o1x = fmaf(h10, w0x, fmaf(h11, w1x, o1x));
            o1y = fmaf(h10, w0y, fmaf(h11, w1y, o1y));
            o1z = fmaf(h10, w0z, fmaf(h11, w1z, o1z));
        }
#pragma unroll
        for (int s = 1; s <= 2; s <<= 1) {
            o0x += __shfl_xor_sync(0xffffffffu, o0x, s);
            o0y += __shfl_xor_sync(0xffffffffu, o0y, s);
            o0z += __shfl_xor_sync(0xffffffffu, o0z, s);
            o1x += __shfl_xor_sync(0xffffffffu, o1x, s);
            o1y += __shfl_xor_sync(0xffffffffu, o1y, s);
            o1z += __shfl_xor_sync(0xffffffffu, o1z, s);
        }
        if (t == 0) {
            float mn0 = (float)(g_bmin[0] - 1) * VOXEL, mx0 = (float)(g_bmax[0] + 1) * VOXEL;
            float mn1 = (float)(g_bmin[1] - 1) * VOXEL, mx1 = (float)(g_bmax[1] + 1) * VOXEL;
            float mn2 = (float)(g_bmin[2] - 1) * VOXEL, mx2 = (float)(g_bmax[2] + 1) * VOXEL;
            int4 c0 = __ldg((const int4*)coords + (n0 + r0l));
            int4 c1c = __ldg((const int4*)coords + (n0 + r1l));
            float* v0 = out + OUT_VOFF + (size_t)(n0 + r0l) * 3;
            float* v1 = out + OUT_VOFF + (size_t)(n0 + r1l) * 3;
            v0[0] = fminf(fmaxf(fmaf((float)c0.y, VOXEL, o0x), mn0), mx0);
            v0[1] = fminf(fmaxf(fmaf((float)c0.z, VOXEL, o0y), mn1), mx1);
            v0[2] = fminf(fmaxf(fmaf((float)c0.w, VOXEL, o0z), mn2), mx2);
            v1[0] = fminf(fmaxf(fmaf((float)c1c.y, VOXEL, o1x), mn0), mx0);
            v1[1] = fminf(fmaxf(fmaf((float)c1c.z, VOXEL, o1y), mn1), mx1);
            v1[2] = fminf(fmaxf(fmaf((float)c1c.w, VOXEL, o1z), mn2), mx2);
        }
    }

    // ---- per-class loop (warp-independent; no barriers) ----
    for (int c = 0; c < NCLS; c++) {
        if (!((orv >> c) & 1u)) {
            // this warp's 16 rows all masked: feat_c == 0 exactly
            // -> ctr = 0, reg = exp(0) = 1, cls = b_cls[c]
            float bc = __ldg(b_cls + c);
            float4 v = (tid & 1) ? make_float4(1.0f, 1.0f, 1.0f, bc)
                                 : make_float4(0.0f, 1.0f, 1.0f, 1.0f);
            ((float4*)(out + ((size_t)c * NPTS + n0) * 8))[tid] = v;   // covers own rows
            continue;   // warp-uniform branch
        }
        // ---- slow path (fully correct; only if some of this warp's rows unmasked) ----
        float cc[8][4];
#pragma unroll
        for (int nb = 0; nb < 8; nb++) { cc[nb][0] = cc[nb][1] = cc[nb][2] = cc[nb][3] = 0.f; }
#pragma unroll
        for (int nb = 0; nb < 8; nb++) {
            const __nv_bfloat16* wn = WCIT[c] + (nb * 8 + g) * WS + 2 * t;
#pragma unroll
            for (int ks = 0; ks < 4; ks++) {
                unsigned b0 = __ldg((const unsigned*)(wn + ks * 16));
                unsigned b1 = __ldg((const unsigned*)(wn + ks * 16 + 8));
                mma16816(cc[nb], af[ks], b0, b1);
            }
        }
        float mk0 = (float)((m0 >> c) & 1u);
        float mk1 = (float)((m1 >> c) & 1u);
        float o0[8], o1[8];
#pragma unroll
        for (int j = 0; j < 8; j++) { o0[j] = 0.f; o1[j] = 0.f; }
#pragma unroll
        for (int nb = 0; nb < 8; nb++) {
            int e0 = nb * 8 + 2 * t, e1 = e0 + 1;
            float ga = __ldg(g_ci + c * CF + e0), ba = __ldg(b_ci + c * CF + e0);
            float gb = __ldg(g_ci + c * CF + e1), bb = __ldg(b_ci + c * CF + e1);
            float f00 = eluf(fmaf(cc[nb][0], ga, ba)) * mk0;
            float f01 = eluf(fmaf(cc[nb][1], gb, bb)) * mk0;
            float f10 = eluf(fmaf(cc[nb][2], ga, ba)) * mk1;
            float f11 = eluf(fmaf(cc[nb][3], gb, bb)) * mk1;
            const float* he0 = &HEADW[c][e0][0];
            const float* he1 = &HEADW[c][e1][0];
#pragma unroll
            for (int j = 0; j < 8; j++) {
                float w0 = __ldg(he0 + j), w1 = __ldg(he1 + j);
                o0[j] = fmaf(f00, w0, fmaf(f01, w1, o0[j]));
                o1[j] = fmaf(f10, w0, fmaf(f11, w1, o1[j]));
            }
        }
#pragma unroll
        for (int s = 1; s <= 2; s <<= 1) {
#pragma unroll
            for (int j = 0; j < 8; j++) {
                o0[j] += __shfl_xor_sync(0xffffffffu, o0[j], s);
                o1[j] += __shfl_xor_sync(0xffffffffu, o1[j], s);
            }
        }
        if (t == 0) {
            float sc = __ldg(scales + c), bc = __ldg(b_cls + c);
            float* p0 = out + ((size_t)c * NPTS + n0 + r0l) * 8;
            float* p1 = out + ((size_t)c * NPTS + n0 + r1l) * 8;
            *(float4*)(p0)     = make_float4(o0[0], __expf(o0[1] * sc), __expf(o0[2] * sc), __expf(o0[3] * sc));
            *(float4*)(p0 + 4) = make_float4(__expf(o0[4] * sc), __expf(o0[5] * sc), __expf(o0[6] * sc), o0[7] + bc);
            *(float4*)(p1)     = make_float4(o1[0], __expf(o1[1] * sc), __expf(o1[2] * sc), __expf(o1[3] * sc));
            *(float4*)(p1 + 4) = make_float4(__expf(o1[4] * sc), __expf(o1[5] * sc), __expf(o1[6] * sc), o1[7] + bc);
        }
    }
}

extern "C" void kernel_launch(void* const* d_in, const int* in_sizes, int n_in,
                              void* d_out, int out_size) {
    const int*   coords = (const int*)d_in[0];
    const float* feats  = (const float*)d_in[1];
    const float* W_sem  = (const float*)d_in[2];
    const float* b_sem  = (const float*)d_in[3];
    const float* W_o1   = (const float*)d_in[4];
    const float* g_o1   = (const float*)d_in[5];
    const float* b_o1   = (const float*)d_in[6];
    const float* W_o2   = (const float*)d_in[7];
    const float* g_o2   = (const float*)d_in[8];
    const float* b_o2   = (const float*)d_in[9];
    const float* W_o3   = (const float*)d_in[10];
    const float* W_ci   = (const float*)d_in[11];
    const float* g_ci   = (const float*)d_in[12];
    const float* b_ci   = (const float*)d_in[13];
    const float* W_ctr  = (const float*)d_in[14];
    const float* W_reg  = (const float*)d_in[15];
    const float* W_cls  = (const float*)d_in[16];
    const float* b_cls  = (const float*)d_in[17];
    const float* scales = (const float*)d_in[18];
    float* out = (float*)d_out;

    k_pre<<<BND_BLKS + PRE_BLKS, 256>>>(coords, W_sem, W_o1, W_o2, W_ci, W_ctr, W_reg, W_cls);
    k_main<<<NTILES, 256>>>(coords, feats, b_sem, g_o1, b_o1, g_o2, b_o2,
                            W_o3, g_ci, b_ci, b_cls, scales, out);
}

// round 9
// speedup vs baseline: 3.0053x; 1.0421x over previous
#include <cuda_runtime.h>
#include <cuda_bf16.h>
#include <math.h>
#include <float.h>

#define NPTS   131072
#define CF     64
#define NCLS   18
#define TILE   128
#define NTILES (NPTS / TILE)
#define VOXEL  0.04f
#define SEM_LOGIT (-1.7346010553881064f)
#define OUT_VOFF ((size_t)NCLS * NPTS * 8)

#define BND_BLKS 264
#define PRE_BLKS 248

// ---- per-thread-fragment-packed bf16 weight images ----
// WB_X[n][t][8]: the 8 B-fragment words for MMA column-row n, thread quad-lane t,
// ordered {ks0_lo, ks0_hi, ks1_lo, ks1_hi, ks2_lo, ks2_hi, ks3_lo, ks3_hi},
// lo = pack(W[n][16ks+2t], W[n][16ks+2t+1]), hi = pack(W[n][16ks+8+2t], W[n][16ks+8+2t+1])
__device__ __align__(16) unsigned WB_SEM[24][4][8];
__device__ __align__(16) unsigned WB_1[64][4][8];
__device__ __align__(16) unsigned WB_2[64][4][8];
__device__ __align__(16) unsigned WB_CI[NCLS][64][4][8];
__device__ float2 G1B1[64];
__device__ float2 G2B2[64];
__device__ float2 GCBC[NCLS][64];
__device__ float4 WO3[64];
__device__ float  THR[24];
__device__ float  HEADW[NCLS][64][8];   // [c][e][{ctr,reg0..5,cls}]

__device__ int g_bmin[3] = {0x7fffffff, 0x7fffffff, 0x7fffffff};
__device__ int g_bmax[3] = {(int)0x80000000, (int)0x80000000, (int)0x80000000};

__device__ __forceinline__ unsigned packbf(float lo, float hi) {
    __nv_bfloat162 p = __floats2bfloat162_rn(lo, hi);
    return *(unsigned*)&p;
}

__global__ void k_pre(const int* __restrict__ coords,
                      const float* __restrict__ W_sem, const float* __restrict__ b_sem,
                      const float* __restrict__ W_o1, const float* __restrict__ g_o1,
                      const float* __restrict__ b_o1, const float* __restrict__ W_o2,
                      const float* __restrict__ g_o2, const float* __restrict__ b_o2,
                      const float* __restrict__ W_o3, const float* __restrict__ W_ci,
                      const float* __restrict__ g_ci, const float* __restrict__ b_ci,
                      const float* __restrict__ W_ctr, const float* __restrict__ W_reg,
                      const float* __restrict__ W_cls) {
    int tid = threadIdx.x;
    if (blockIdx.x < BND_BLKS) {
        // ---- scene bounds ----
        __shared__ int smin[3], smax[3];
        if (tid < 3) { smin[tid] = 0x7fffffff; smax[tid] = (int)0x80000000; }
        __syncthreads();
        int l0 = 0x7fffffff, l1 = 0x7fffffff, l2 = 0x7fffffff;
        int h0 = (int)0x80000000, h1 = (int)0x80000000, h2 = (int)0x80000000;
        for (int i = blockIdx.x * 256 + tid; i < NPTS; i += BND_BLKS * 256) {
            int4 cr = __ldg((const int4*)coords + i);
            l0 = min(l0, cr.y); h0 = max(h0, cr.y);
            l1 = min(l1, cr.z); h1 = max(h1, cr.z);
            l2 = min(l2, cr.w); h2 = max(h2, cr.w);
        }
        l0 = __reduce_min_sync(0xffffffffu, l0); h0 = __reduce_max_sync(0xffffffffu, h0);
        l1 = __reduce_min_sync(0xffffffffu, l1); h1 = __reduce_max_sync(0xffffffffu, h1);
        l2 = __reduce_min_sync(0xffffffffu, l2); h2 = __reduce_max_sync(0xffffffffu, h2);
        if ((tid & 31) == 0) {
            atomicMin(&smin[0], l0); atomicMax(&smax[0], h0);
            atomicMin(&smin[1], l1); atomicMax(&smax[1], h1);
            atomicMin(&smin[2], l2); atomicMax(&smax[2], h2);
        }
        __syncthreads();
        if (tid < 3) { atomicMin(&g_bmin[tid], smin[tid]); atomicMax(&g_bmax[tid], smax[tid]); }
    } else {
        int i0 = (blockIdx.x - BND_BLKS) * 256 + tid;
        int stride = PRE_BLKS * 256;
        // sem image (n padded to 24; zeros beyond NCLS)
        for (int i = i0; i < 24 * 32; i += stride) {
            int n = i >> 5, r = i & 31;
            int tt = r >> 3, idx = r & 7;
            int ks = idx >> 1, half = idx & 1;
            int k = 16 * ks + 8 * half + 2 * tt;
            float w0 = (n < NCLS) ? __ldg(W_sem + k * NCLS + n) : 0.0f;
            float w1 = (n < NCLS) ? __ldg(W_sem + (k + 1) * NCLS + n) : 0.0f;
            WB_SEM[n][tt][idx] = packbf(w0, w1);
        }
        // l1 / l2 images
        for (int i = i0; i < 64 * 32; i += stride) {
            int n = i >> 5, r = i & 31;
            int tt = r >> 3, idx = r & 7;
            int ks = idx >> 1, half = idx & 1;
            int k = 16 * ks + 8 * half + 2 * tt;
            WB_1[n][tt][idx] = packbf(__ldg(W_o1 + k * 64 + n), __ldg(W_o1 + (k + 1) * 64 + n));
            WB_2[n][tt][idx] = packbf(__ldg(W_o2 + k * 64 + n), __ldg(W_o2 + (k + 1) * 64 + n));
        }
        // per-class images
        for (int i = i0; i < NCLS * 64 * 32; i += stride) {
            int c = i / 2048, r2 = i % 2048;
            int n = r2 >> 5, r = r2 & 31;
            int tt = r >> 3, idx = r & 7;
            int ks = idx >> 1, half = idx & 1;
            int k = 16 * ks + 8 * half + 2 * tt;
            const float* Wc = W_ci + (size_t)c * 4096;
            WB_CI[c][n][tt][idx] = packbf(__ldg(Wc + k * 64 + n), __ldg(Wc + (k + 1) * 64 + n));
        }
        // BN params, W_o3, thresholds
        for (int e = i0; e < 64; e += stride) {
            G1B1[e] = make_float2(__ldg(g_o1 + e), __ldg(b_o1 + e));
            G2B2[e] = make_float2(__ldg(g_o2 + e), __ldg(b_o2 + e));
            WO3[e]  = make_float4(__ldg(W_o3 + 3 * e), __ldg(W_o3 + 3 * e + 1),
                                  __ldg(W_o3 + 3 * e + 2), 0.0f);
        }
        for (int e = i0; e < 24; e += stride)
            THR[e] = (e < NCLS) ? (SEM_LOGIT - __ldg(b_sem + e)) : FLT_MAX;
        for (int i = i0; i < NCLS * 64; i += stride) {
            int c = i >> 6, e = i & 63;
            GCBC[c][e] = make_float2(__ldg(g_ci + c * CF + e), __ldg(b_ci + c * CF + e));
        }
        for (int i = i0; i < NCLS * 64 * 8; i += stride) {
            int c = i >> 9, r = i & 511;
            int e = r >> 3, j = r & 7;
            float v;
            if (j == 0)      v = __ldg(W_ctr + e);
            else if (j < 7)  v = __ldg(W_reg + e * 6 + (j - 1));
            else             v = __ldg(W_cls + e * NCLS + c);
            HEADW[c][e][j] = v;
        }
    }
}

__device__ __forceinline__ float eluf(float x) { return x > 0.0f ? x : (__expf(x) - 1.0f); }

// D(16x8,f32) += A(16x16,bf16 row) x B(16x8,bf16 col)
__device__ __forceinline__ void mma16816(float* c, const unsigned* a, unsigned b0, unsigned b1) {
    asm volatile("mma.sync.aligned.m16n8k16.row.col.f32.bf16.bf16.f32 "
                 "{%0,%1,%2,%3}, {%4,%5,%6,%7}, {%8,%9}, {%0,%1,%2,%3};"
                 : "+f"(c[0]), "+f"(c[1]), "+f"(c[2]), "+f"(c[3])
                 : "r"(a[0]), "r"(a[1]), "r"(a[2]), "r"(a[3]), "r"(b0), "r"(b1));
}

// 4 k-blocks of MMA for one n-row using two uint4 weight loads
__device__ __forceinline__ void mma_nrow(float* c, const unsigned af[4][4], const unsigned* wp) {
    uint4 wa = __ldg((const uint4*)wp);
    uint4 wb = __ldg((const uint4*)wp + 1);
    mma16816(c, af[0], wa.x, wa.y);
    mma16816(c, af[1], wa.z, wa.w);
    mma16816(c, af[2], wb.x, wb.y);
    mma16816(c, af[3], wb.z, wb.w);
}

// A fragment from fp32 global rows (row-major, k contiguous)
__device__ __forceinline__ void ldfragA(const float* b0, const float* b1, int kb, unsigned* a) {
    float2 f0 = __ldg((const float2*)(b0 + kb));
    float2 f1 = __ldg((const float2*)(b1 + kb));
    float2 f2 = __ldg((const float2*)(b0 + kb + 8));
    float2 f3 = __ldg((const float2*)(b1 + kb + 8));
    a[0] = packbf(f0.x, f0.y); a[1] = packbf(f1.x, f1.y);
    a[2] = packbf(f2.x, f2.y); a[3] = packbf(f3.x, f3.y);
}

__global__ __launch_bounds__(256, 3)
void k_main(const int* __restrict__ coords, const float* __restrict__ feats,
            const float* __restrict__ b_cls, const float* __restrict__ scales,
            float* __restrict__ out)
{
    const int tid  = threadIdx.x;
    const int w    = tid >> 5;
    const int lane = tid & 31;
    const int g    = lane >> 2;
    const int t    = lane & 3;
    const int n0   = blockIdx.x * TILE;
    const int r0l  = w * 16 + g;      // local rows this thread covers
    const int r1l  = r0l + 8;

    // ---- A fragments straight from global fp32 feats ----
    unsigned af[4][4];
    {
        const float* fb0 = feats + (size_t)(n0 + r0l) * CF + 2 * t;
        const float* fb1 = feats + (size_t)(n0 + r1l) * CF + 2 * t;
#pragma unroll
        for (int ks = 0; ks < 4; ks++) ldfragA(fb0, fb1, ks * 16, af[ks]);
    }

    // ---- sem GEMM (N=24 covers 18 classes) -> per-row mask bits ----
    unsigned m0 = 0, m1 = 0;
#pragma unroll
    for (int nb = 0; nb < 3; nb++) {
        float cs[4] = {0.f, 0.f, 0.f, 0.f};
        mma_nrow(cs, af, &WB_SEM[nb * 8 + g][t][0]);
        int e0 = nb * 8 + 2 * t, e1 = e0 + 1;
        float th0 = __ldg(THR + e0), th1 = __ldg(THR + e1);
        if (cs[0] > th0) m0 |= 1u << e0;
        if (cs[2] > th0) m1 |= 1u << e0;
        if (cs[1] > th1) m0 |= 1u << e1;
        if (cs[3] > th1) m1 |= 1u << e1;
    }
    // quad-OR: every thread gets full mask for its two rows
    m0 |= __shfl_xor_sync(0xffffffffu, m0, 1); m0 |= __shfl_xor_sync(0xffffffffu, m0, 2);
    m1 |= __shfl_xor_sync(0xffffffffu, m1, 1); m1 |= __shfl_xor_sync(0xffffffffu, m1, 2);
    const unsigned orv = __reduce_or_sync(0xffffffffu, m0 | m1);

    // ---- l1 GEMM -> registers ----
    float c1[8][4];
#pragma unroll
    for (int nb = 0; nb < 8; nb++) { c1[nb][0] = c1[nb][1] = c1[nb][2] = c1[nb][3] = 0.f; }
#pragma unroll
    for (int nb = 0; nb < 8; nb++) mma_nrow(c1[nb], af, &WB_1[nb * 8 + g][t][0]);

    // ---- BN+ELU(l1) -> l2 A-fragments ENTIRELY IN REGISTERS ----
    unsigned a2[4][4];
#pragma unroll
    for (int ks = 0; ks < 4; ks++) {
        int nA = 2 * ks, nB = 2 * ks + 1;
        int eA0 = nA * 8 + 2 * t, eB0 = nB * 8 + 2 * t;
        float2 gbA0 = __ldg(&G1B1[eA0]), gbA1 = __ldg(&G1B1[eA0 + 1]);
        float2 gbB0 = __ldg(&G1B1[eB0]), gbB1 = __ldg(&G1B1[eB0 + 1]);
        a2[ks][0] = packbf(eluf(fmaf(c1[nA][0], gbA0.x, gbA0.y)), eluf(fmaf(c1[nA][1], gbA1.x, gbA1.y)));
        a2[ks][1] = packbf(eluf(fmaf(c1[nA][2], gbA0.x, gbA0.y)), eluf(fmaf(c1[nA][3], gbA1.x, gbA1.y)));
        a2[ks][2] = packbf(eluf(fmaf(c1[nB][0], gbB0.x, gbB0.y)), eluf(fmaf(c1[nB][1], gbB1.x, gbB1.y)));
        a2[ks][3] = packbf(eluf(fmaf(c1[nB][2], gbB0.x, gbB0.y)), eluf(fmaf(c1[nB][3], gbB1.x, gbB1.y)));
    }

    // ---- l2 GEMM + BN/ELU + l3 dot + voted ----
    {
        float o0x = 0.f, o0y = 0.f, o0z = 0.f, o1x = 0.f, o1y = 0.f, o1z = 0.f;
#pragma unroll
        for (int nb = 0; nb < 8; nb++) {
            float c2[4] = {0.f, 0.f, 0.f, 0.f};
            mma_nrow(c2, a2, &WB_2[nb * 8 + g][t][0]);
            int e0 = nb * 8 + 2 * t;
            float2 gb0 = __ldg(&G2B2[e0]), gb1 = __ldg(&G2B2[e0 + 1]);
            float h00 = eluf(fmaf(c2[0], gb0.x, gb0.y)), h01 = eluf(fmaf(c2[1], gb1.x, gb1.y));
            float h10 = eluf(fmaf(c2[2], gb0.x, gb0.y)), h11 = eluf(fmaf(c2[3], gb1.x, gb1.y));
            float4 w0 = __ldg(&WO3[e0]), w1 = __ldg(&WO3[e0 + 1]);
            o0x = fmaf(h00, w0.x, fmaf(h01, w1.x, o0x));
            o0y = fmaf(h00, w0.y, fmaf(h01, w1.y, o0y));
            o0z = fmaf(h00, w0.z, fmaf(h01, w1.z, o0z));
            o1x = fmaf(h10, w0.x, fmaf(h11, w1.x, o1x));
            o1y = fmaf(h10, w0.y, fmaf(h11, w1.y, o1y));
            o1z = fmaf(h10, w0.z, fmaf(h11, w1.z, o1z));
        }
#pragma unroll
        for (int s = 1; s <= 2; s <<= 1) {
            o0x += __shfl_xor_sync(0xffffffffu, o0x, s);
            o0y += __shfl_xor_sync(0xffffffffu, o0y, s);
            o0z += __shfl_xor_sync(0xffffffffu, o0z, s);
            o1x += __shfl_xor_sync(0xffffffffu, o1x, s);
            o1y += __shfl_xor_sync(0xffffffffu, o1y, s);
            o1z += __shfl_xor_sync(0xffffffffu, o1z, s);
        }
        if (t == 0) {
            float mn0 = (float)(g_bmin[0] - 1) * VOXEL, mx0 = (float)(g_bmax[0] + 1) * VOXEL;
            float mn1 = (float)(g_bmin[1] - 1) * VOXEL, mx1 = (float)(g_bmax[1] + 1) * VOXEL;
            float mn2 = (float)(g_bmin[2] - 1) * VOXEL, mx2 = (float)(g_bmax[2] + 1) * VOXEL;
            int4 c0 = __ldg((const int4*)coords + (n0 + r0l));
            int4 c1c = __ldg((const int4*)coords + (n0 + r1l));
            float* v0 = out + OUT_VOFF + (size_t)(n0 + r0l) * 3;
            float* v1 = out + OUT_VOFF + (size_t)(n0 + r1l) * 3;
            v0[0] = fminf(fmaxf(fmaf((float)c0.y, VOXEL, o0x), mn0), mx0);
            v0[1] = fminf(fmaxf(fmaf((float)c0.z, VOXEL, o0y), mn1), mx1);
            v0[2] = fminf(fmaxf(fmaf((float)c0.w, VOXEL, o0z), mn2), mx2);
            v1[0] = fminf(fmaxf(fmaf((float)c1c.y, VOXEL, o1x), mn0), mx0);
            v1[1] = fminf(fmaxf(fmaf((float)c1c.z, VOXEL, o1y), mn1), mx1);
            v1[2] = fminf(fmaxf(fmaf((float)c1c.w, VOXEL, o1z), mn2), mx2);
        }
    }

    // ---- per-class loop (warp-independent; no barriers) ----
    for (int c = 0; c < NCLS; c++) {
        if (!((orv >> c) & 1u)) {
            // this warp's 16 rows all masked: feat_c == 0 exactly
            // -> ctr = 0, reg = exp(0) = 1, cls = b_cls[c]
            float bc = __ldg(b_cls + c);
            float4 v = (tid & 1) ? make_float4(1.0f, 1.0f, 1.0f, bc)
                                 : make_float4(0.0f, 1.0f, 1.0f, 1.0f);
            ((float4*)(out + ((size_t)c * NPTS + n0) * 8))[tid] = v;   // covers own rows
            continue;   // warp-uniform branch
        }
        // ---- slow path (fully correct; only if some of this warp's rows unmasked) ----
        float cc[8][4];
#pragma unroll
        for (int nb = 0; nb < 8; nb++) { cc[nb][0] = cc[nb][1] = cc[nb][2] = cc[nb][3] = 0.f; }
#pragma unroll
        for (int nb = 0; nb < 8; nb++) mma_nrow(cc[nb], af, &WB_CI[c][nb * 8 + g][t][0]);
        float mk0 = (float)((m0 >> c) & 1u);
        float mk1 = (float)((m1 >> c) & 1u);
        float o0[8], o1[8];
#pragma unroll
        for (int j = 0; j < 8; j++) { o0[j] = 0.f; o1[j] = 0.f; }
#pragma unroll
        for (int nb = 0; nb < 8; nb++) {
            int e0 = nb * 8 + 2 * t;
            float2 gb0 = __ldg(&GCBC[c][e0]), gb1 = __ldg(&GCBC[c][e0 + 1]);
            float f00 = eluf(fmaf(cc[nb][0], gb0.x, gb0.y)) * mk0;
            float f01 = eluf(fmaf(cc[nb][1], gb1.x, gb1.y)) * mk0;
            float f10 = eluf(fmaf(cc[nb][2], gb0.x, gb0.y)) * mk1;
            float f11 = eluf(fmaf(cc[nb][3], gb1.x, gb1.y)) * mk1;
            const float* he0 = &HEADW[c][e0][0];
            const float* he1 = &HEADW[c][e0 + 1][0];
#pragma unroll
            for (int j = 0; j < 8; j++) {
                float w0 = __ldg(he0 + j), w1 = __ldg(he1 + j);
                o0[j] = fmaf(f00, w0, fmaf(f01, w1, o0[j]));
                o1[j] = fmaf(f10, w0, fmaf(f11, w1, o1[j]));
            }
        }
#pragma unroll
        for (int s = 1; s <= 2; s <<= 1) {
#pragma unroll
            for (int j = 0; j < 8; j++) {
                o0[j] += __shfl_xor_sync(0xffffffffu, o0[j], s);
                o1[j] += __shfl_xor_sync(0xffffffffu, o1[j], s);
            }
        }
        if (t == 0) {
            float sc = __ldg(scales + c), bc = __ldg(b_cls + c);
            float* p0 = out + ((size_t)c * NPTS + n0 + r0l) * 8;
            float* p1 = out + ((size_t)c * NPTS + n0 + r1l) * 8;
            *(float4*)(p0)     = make_float4(o0[0], __expf(o0[1] * sc), __expf(o0[2] * sc), __expf(o0[3] * sc));
            *(float4*)(p0 + 4) = make_float4(__expf(o0[4] * sc), __expf(o0[5] * sc), __expf(o0[6] * sc), o0[7] + bc);
            *(float4*)(p1)     = make_float4(o1[0], __expf(o1[1] * sc), __expf(o1[2] * sc), __expf(o1[3] * sc));
            *(float4*)(p1 + 4) = make_float4(__expf(o1[4] * sc), __expf(o1[5] * sc), __expf(o1[6] * sc), o1[7] + bc);
        }
    }
}

extern "C" void kernel_launch(void* const* d_in, const int* in_sizes, int n_in,
                              void* d_out, int out_size) {
    const int*   coords = (const int*)d_in[0];
    const float* feats  = (const float*)d_in[1];
    const float* W_sem  = (const float*)d_in[2];
    const float* b_sem  = (const float*)d_in[3];
    const float* W_o1   = (const float*)d_in[4];
    const float* g_o1   = (const float*)d_in[5];
    const float* b_o1   = (const float*)d_in[6];
    const float* W_o2   = (const float*)d_in[7];
    const float* g_o2   = (const float*)d_in[8];
    const float* b_o2   = (const float*)d_in[9];
    const float* W_o3   = (const float*)d_in[10];
    const float* W_ci   = (const float*)d_in[11];
    const float* g_ci   = (const float*)d_in[12];
    const float* b_ci   = (const float*)d_in[13];
    const float* W_ctr  = (const float*)d_in[14];
    const float* W_reg  = (const float*)d_in[15];
    const float* W_cls  = (const float*)d_in[16];
    const float* b_cls  = (const float*)d_in[17];
    const float* scales = (const float*)d_in[18];
    float* out = (float*)d_out;

    k_pre<<<BND_BLKS + PRE_BLKS, 256>>>(coords, W_sem, b_sem, W_o1, g_o1, b_o1,
                                        W_o2, g_o2, b_o2, W_o3, W_ci, g_ci, b_ci,
                                        W_ctr, W_reg, W_cls);
    k_main<<<NTILES, 256>>>(coords, feats, b_cls, scales, out);
}